// round 3
// baseline (speedup 1.0000x reference)
#include <cuda_runtime.h>
#include <cuda_bf16.h>
#include <math.h>

// ---------------- problem constants ----------------
#define NQ      21760          // num queries == num keys
#define EMBED   256
#define NH      8
#define HD      32
#define NL      4
#define NP      4
#define KDIM    256            // K for all GEMMs

__device__ __constant__ int c_start[NL] = {0, 16384, 20480, 21504};
__device__ __constant__ int c_HW[NL]    = {128, 64, 32, 16};   // square levels

// ---------------- scratch (device globals; no allocations allowed) --------
__device__ float g_q   [NQ * EMBED];   // query + query_pos
__device__ float g_v   [NQ * EMBED];   // projected value (key, h*32+d)
__device__ float g_off [NQ * 256];     // sampling offsets (q, h*32 + lvl*8 + p*2 + xy)
__device__ float g_attn[NQ * 128];     // attn logits -> weights (q, h*16 + lvl*4 + p)
__device__ float g_samp[NQ * EMBED];   // sampled (q, h*32 + d)

// ---------------- elementwise add: q = query + query_pos ----------------
__global__ void __launch_bounds__(256) add_kernel(
    const float* __restrict__ a, const float* __restrict__ b,
    float* __restrict__ c, int n4)
{
    int i = blockIdx.x * blockDim.x + threadIdx.x;
    if (i >= n4) return;
    float4 x = reinterpret_cast<const float4*>(a)[i];
    float4 y = reinterpret_cast<const float4*>(b)[i];
    x.x += y.x; x.y += y.y; x.z += y.z; x.w += y.w;
    reinterpret_cast<float4*>(c)[i] = x;
}

// ---------------- tiled fp32 GEMM: C[M,N] = A[M,K=256] @ W[N,K]^T + bias (+ident)
// BM=BN=64, BK=16, 256 threads, 4x4 per thread. M % 64 == 0, N % 64 == 0.
#define BM 64
#define BN 64
#define BK 16
__global__ void __launch_bounds__(256) gemm_kernel(
    const float* __restrict__ A, const float* __restrict__ W,
    const float* __restrict__ bias, const float* __restrict__ ident,
    float* __restrict__ C, int N)
{
    __shared__ float As[BK][BM];
    __shared__ float Ws[BK][BN];

    const int bx = blockIdx.x;        // N tile
    const int by = blockIdx.y;        // M tile
    const int tid = threadIdx.x;
    const int tx = tid & 15;          // 0..15 -> 4 cols each
    const int ty = tid >> 4;          // 0..15 -> 4 rows each

    // global load mapping: each thread one float4 of A tile and one of W tile
    const int lr = tid >> 2;          // 0..63  row within tile
    const int lc = (tid & 3) * 4;     // 0,4,8,12 k offset
    const float* Ap = A + (size_t)(by * BM + lr) * KDIM + lc;
    const float* Wp = W + (size_t)(bx * BN + lr) * KDIM + lc;

    float acc[4][4] = {};

    for (int k0 = 0; k0 < KDIM; k0 += BK) {
        float4 a4 = *reinterpret_cast<const float4*>(Ap + k0);
        float4 w4 = *reinterpret_cast<const float4*>(Wp + k0);
        __syncthreads();
        As[lc + 0][lr] = a4.x; As[lc + 1][lr] = a4.y;
        As[lc + 2][lr] = a4.z; As[lc + 3][lr] = a4.w;
        Ws[lc + 0][lr] = w4.x; Ws[lc + 1][lr] = w4.y;
        Ws[lc + 2][lr] = w4.z; Ws[lc + 3][lr] = w4.w;
        __syncthreads();
        #pragma unroll
        for (int k = 0; k < BK; k++) {
            float ar[4], wr[4];
            #pragma unroll
            for (int i = 0; i < 4; i++) ar[i] = As[k][ty * 4 + i];
            #pragma unroll
            for (int j = 0; j < 4; j++) wr[j] = Ws[k][tx * 4 + j];
            #pragma unroll
            for (int i = 0; i < 4; i++)
                #pragma unroll
                for (int j = 0; j < 4; j++)
                    acc[i][j] = fmaf(ar[i], wr[j], acc[i][j]);
        }
    }

    #pragma unroll
    for (int i = 0; i < 4; i++) {
        int m = by * BM + ty * 4 + i;
        #pragma unroll
        for (int j = 0; j < 4; j++) {
            int n = bx * BN + tx * 4 + j;
            float v = acc[i][j] + bias[n];
            if (ident) v += ident[(size_t)m * N + n];
            C[(size_t)m * N + n] = v;
        }
    }
}

// ---------------- softmax over last 16 (per query-head) ----------------
__global__ void __launch_bounds__(256) softmax16_kernel(float* __restrict__ attn, int rows)
{
    int r = blockIdx.x * blockDim.x + threadIdx.x;
    if (r >= rows) return;
    float* a = attn + (size_t)r * 16;
    float v[16];
    float4* a4 = reinterpret_cast<float4*>(a);
    #pragma unroll
    for (int i = 0; i < 4; i++) {
        float4 t = a4[i];
        v[i*4+0] = t.x; v[i*4+1] = t.y; v[i*4+2] = t.z; v[i*4+3] = t.w;
    }
    float mx = v[0];
    #pragma unroll
    for (int i = 1; i < 16; i++) mx = fmaxf(mx, v[i]);
    float s = 0.f;
    #pragma unroll
    for (int i = 0; i < 16; i++) { v[i] = __expf(v[i] - mx); s += v[i]; }
    float inv = 1.f / s;
    #pragma unroll
    for (int i = 0; i < 4; i++) {
        float4 t;
        t.x = v[i*4+0]*inv; t.y = v[i*4+1]*inv; t.z = v[i*4+2]*inv; t.w = v[i*4+3]*inv;
        a4[i] = t;
    }
}

// ---------------- deformable sampling: warp per (q, head), lane = channel ----
__global__ void __launch_bounds__(256) sample_kernel(
    const float* __restrict__ v, const float* __restrict__ ref,
    const float* __restrict__ off, const float* __restrict__ attn,
    float* __restrict__ out)
{
    int warp = (blockIdx.x * blockDim.x + threadIdx.x) >> 5;
    int lane = threadIdx.x & 31;
    if (warp >= NQ * NH) return;
    int q = warp >> 3;
    int h = warp & 7;

    const float* offq = off  + (size_t)q * 256 + h * 32;
    const float* attq = attn + (size_t)q * 128 + h * 16;
    const float* vh   = v + h * 32 + lane;

    float acc = 0.f;
    #pragma unroll
    for (int lvl = 0; lvl < NL; lvl++) {
        const int HW = c_HW[lvl];
        const int start = c_start[lvl];
        const float fHW = (float)HW;
        const float rx = ref[(size_t)q * 8 + lvl * 2 + 0];
        const float ry = ref[(size_t)q * 8 + lvl * 2 + 1];
        #pragma unroll
        for (int p = 0; p < NP; p++) {
            float ox = offq[lvl * 8 + p * 2 + 0];
            float oy = offq[lvl * 8 + p * 2 + 1];
            float aw = attq[lvl * 4 + p];
            // pixel coords: loc*HW - 0.5  (grid_sample align_corners=False)
            float gx = fmaf(rx, fHW, ox - 0.5f);
            float gy = fmaf(ry, fHW, oy - 0.5f);
            float x0f = floorf(gx), y0f = floorf(gy);
            float wx = gx - x0f, wy = gy - y0f;
            int x0 = (int)x0f, y0 = (int)y0f;

            float s = 0.f;
            bool vx0 = (x0 >= 0) & (x0 < HW);
            bool vx1 = (x0 + 1 >= 0) & (x0 + 1 < HW);
            if (y0 >= 0 && y0 < HW) {
                size_t rowb = (size_t)(start + y0 * HW) * 256;
                if (vx0) s = fmaf((1.f - wx) * (1.f - wy), vh[rowb + (size_t)x0 * 256], s);
                if (vx1) s = fmaf(wx * (1.f - wy),         vh[rowb + (size_t)(x0 + 1) * 256], s);
            }
            if (y0 + 1 >= 0 && y0 + 1 < HW) {
                size_t rowb = (size_t)(start + (y0 + 1) * HW) * 256;
                if (vx0) s = fmaf((1.f - wx) * wy, vh[rowb + (size_t)x0 * 256], s);
                if (vx1) s = fmaf(wx * wy,         vh[rowb + (size_t)(x0 + 1) * 256], s);
            }
            acc = fmaf(aw, s, acc);
        }
    }
    out[(size_t)q * 256 + h * 32 + lane] = acc;
}

// ---------------- host launch ----------------
static float* sym_addr(const void* sym)
{
    void* p = nullptr;
    cudaGetSymbolAddress(&p, sym);
    return (float*)p;
}

extern "C" void kernel_launch(void* const* d_in, const int* in_sizes, int n_in,
                              void* d_out, int out_size)
{
    const float* query     = (const float*)d_in[0];
    const float* query_pos = (const float*)d_in[1];
    const float* value     = (const float*)d_in[2];
    const float* refpts    = (const float*)d_in[3];
    // d_in[4]: spatial_shapes (int32) — compile-time constants here
    const float* W_value   = (const float*)d_in[5];
    const float* b_value   = (const float*)d_in[6];
    const float* W_off     = (const float*)d_in[7];
    const float* b_off     = (const float*)d_in[8];
    const float* W_attn    = (const float*)d_in[9];
    const float* b_attn    = (const float*)d_in[10];
    const float* W_out     = (const float*)d_in[11];
    const float* b_out     = (const float*)d_in[12];
    float* out = (float*)d_out;

    float* q    = sym_addr(g_q);
    float* v    = sym_addr(g_v);
    float* off  = sym_addr(g_off);
    float* attn = sym_addr(g_attn);
    float* samp = sym_addr(g_samp);

    // 1) q = query + query_pos
    {
        int n4 = NQ * EMBED / 4;
        add_kernel<<<(n4 + 255) / 256, 256>>>(query, query_pos, q, n4);
    }
    // 2) v = value @ W_value^T + b_value   (N=256)
    {
        dim3 grid(256 / BN, NQ / BM);
        gemm_kernel<<<grid, 256>>>(value, W_value, b_value, nullptr, v, 256);
    }
    // 3) offsets = q @ W_off^T + b_off     (N=256)
    {
        dim3 grid(256 / BN, NQ / BM);
        gemm_kernel<<<grid, 256>>>(q, W_off, b_off, nullptr, off, 256);
    }
    // 4) attn logits = q @ W_attn^T + b_attn  (N=128)
    {
        dim3 grid(128 / BN, NQ / BM);
        gemm_kernel<<<grid, 256>>>(q, W_attn, b_attn, nullptr, attn, 128);
    }
    // 5) softmax over 16 points per (q, head)
    {
        int rows = NQ * NH;
        softmax16_kernel<<<(rows + 255) / 256, 256>>>(attn, rows);
    }
    // 6) deformable bilinear sampling -> samp
    {
        int warps = NQ * NH;                   // one warp per (q, head)
        int threads = warps * 32;
        sample_kernel<<<threads / 256, 256>>>(v, refpts, off, attn, samp);
    }
    // 7) out = samp @ W_out^T + b_out + query  (residual), straight to d_out
    {
        dim3 grid(256 / BN, NQ / BM);
        gemm_kernel<<<grid, 256>>>(samp, W_out, b_out, query, out, 256);
    }
}

// round 4
// speedup vs baseline: 1.1149x; 1.1149x over previous
#include <cuda_runtime.h>
#include <cuda_fp16.h>
#include <math.h>

// ---------------- problem constants ----------------
#define NQ      21760          // num queries == num keys
#define EMBED   256
#define NH      8
#define HD      32
#define NL      4
#define NP      4
#define KDIM    256            // K for all GEMMs

__device__ __constant__ int c_start[NL] = {0, 16384, 20480, 21504};
__device__ __constant__ int c_HW[NL]    = {128, 64, 32, 16};   // square levels

// ---------------- scratch (device globals; no allocations allowed) --------
__device__ __half g_vh [NQ * EMBED];   // projected value in fp16 (key, h*32+d)
__device__ float  g_off [NQ * 256];    // sampling offsets (q, h*32 + pt*2 + xy)
__device__ float  g_attn[NQ * 128];    // attn logits (q, h*16 + pt)
__device__ float  g_samp[NQ * EMBED];  // sampled (q, h*32 + d)

// ---------------- SGEMM 128x128x8, 256 threads, 8x8 microtile ----------------
// C[M,N] = (A (+A2)) @ W[N,K]^T + bias (+ident). M%128==0, N%128==0, K=256.
// If Ch != null, writes __half to Ch instead of float to C.
#define GBM 128
#define GBN 128
#define GBK 8

__global__ void __launch_bounds__(256) gemm128(
    const float* __restrict__ A, const float* __restrict__ A2,
    const float* __restrict__ W, const float* __restrict__ bias,
    const float* __restrict__ ident,
    float* __restrict__ C, __half* __restrict__ Ch, int N)
{
    __shared__ float As[GBK][GBM];
    __shared__ float Ws[GBK][GBN];

    const int tid = threadIdx.x;
    const int bx = blockIdx.x;        // N tile
    const int by = blockIdx.y;        // M tile

    // global load mapping: each thread one float4 of A tile and one of W tile
    const int lr = tid >> 1;          // 0..127 row within tile
    const int lc = (tid & 1) * 4;     // 0 or 4, k offset
    const float* Ap  = A + (size_t)(by * GBM + lr) * KDIM + lc;
    const float* A2p = A2 ? A2 + (size_t)(by * GBM + lr) * KDIM + lc : nullptr;
    const float* Wp  = W + (size_t)(bx * GBN + lr) * KDIM + lc;

    const int tx = tid & 15;          // n group: cols tx*8..+7
    const int ty = tid >> 4;          // m group: rows ty*8..+7

    float acc[8][8] = {};

    float4 a4 = *reinterpret_cast<const float4*>(Ap);
    if (A2p) {
        float4 t = *reinterpret_cast<const float4*>(A2p);
        a4.x += t.x; a4.y += t.y; a4.z += t.z; a4.w += t.w;
    }
    float4 w4 = *reinterpret_cast<const float4*>(Wp);

    for (int k0 = 0; k0 < KDIM; k0 += GBK) {
        As[lc + 0][lr] = a4.x; As[lc + 1][lr] = a4.y;
        As[lc + 2][lr] = a4.z; As[lc + 3][lr] = a4.w;
        Ws[lc + 0][lr] = w4.x; Ws[lc + 1][lr] = w4.y;
        Ws[lc + 2][lr] = w4.z; Ws[lc + 3][lr] = w4.w;
        __syncthreads();

        if (k0 + GBK < KDIM) {
            a4 = *reinterpret_cast<const float4*>(Ap + k0 + GBK);
            if (A2p) {
                float4 t = *reinterpret_cast<const float4*>(A2p + k0 + GBK);
                a4.x += t.x; a4.y += t.y; a4.z += t.z; a4.w += t.w;
            }
            w4 = *reinterpret_cast<const float4*>(Wp + k0 + GBK);
        }

        #pragma unroll
        for (int k = 0; k < GBK; k++) {
            float4 af0 = *reinterpret_cast<const float4*>(&As[k][ty * 8]);
            float4 af1 = *reinterpret_cast<const float4*>(&As[k][ty * 8 + 4]);
            float4 bf0 = *reinterpret_cast<const float4*>(&Ws[k][tx * 8]);
            float4 bf1 = *reinterpret_cast<const float4*>(&Ws[k][tx * 8 + 4]);
            float ar[8] = {af0.x, af0.y, af0.z, af0.w, af1.x, af1.y, af1.z, af1.w};
            float br[8] = {bf0.x, bf0.y, bf0.z, bf0.w, bf1.x, bf1.y, bf1.z, bf1.w};
            #pragma unroll
            for (int i = 0; i < 8; i++)
                #pragma unroll
                for (int j = 0; j < 8; j++)
                    acc[i][j] = fmaf(ar[i], br[j], acc[i][j]);
        }
        __syncthreads();
    }

    // bias for this thread's 8 columns
    const int nbase = bx * GBN + tx * 8;
    float4 bb0 = *reinterpret_cast<const float4*>(bias + nbase);
    float4 bb1 = *reinterpret_cast<const float4*>(bias + nbase + 4);
    float bv[8] = {bb0.x, bb0.y, bb0.z, bb0.w, bb1.x, bb1.y, bb1.z, bb1.w};

    #pragma unroll
    for (int i = 0; i < 8; i++) {
        int m = by * GBM + ty * 8 + i;
        float r[8];
        #pragma unroll
        for (int j = 0; j < 8; j++) r[j] = acc[i][j] + bv[j];
        if (ident) {
            float4 i0 = *reinterpret_cast<const float4*>(ident + (size_t)m * N + nbase);
            float4 i1 = *reinterpret_cast<const float4*>(ident + (size_t)m * N + nbase + 4);
            r[0]+=i0.x; r[1]+=i0.y; r[2]+=i0.z; r[3]+=i0.w;
            r[4]+=i1.x; r[5]+=i1.y; r[6]+=i1.z; r[7]+=i1.w;
        }
        if (Ch) {
            __half2* hp = reinterpret_cast<__half2*>(Ch + (size_t)m * N + nbase);
            #pragma unroll
            for (int j = 0; j < 4; j++)
                hp[j] = __floats2half2_rn(r[2*j], r[2*j+1]);
        } else {
            float4* cp = reinterpret_cast<float4*>(C + (size_t)m * N + nbase);
            cp[0] = make_float4(r[0], r[1], r[2], r[3]);
            cp[1] = make_float4(r[4], r[5], r[6], r[7]);
        }
    }
}

// ---------------- deformable sampling + fused softmax ----------------
// warp per (q, head-pair); half-warp per head: 16 lanes x half2 = 32 channels.
// lane li (0..15) also owns point li for the inline 16-wide softmax.
__global__ void __launch_bounds__(256) sample_kernel(
    const __half2* __restrict__ v, const float* __restrict__ ref,
    const float* __restrict__ off, const float* __restrict__ logits,
    float* __restrict__ out)
{
    const int gwarp = (blockIdx.x * blockDim.x + threadIdx.x) >> 5;
    const int lane = threadIdx.x & 31;
    if (gwarp >= NQ * 4) return;
    const int q  = gwarp >> 2;
    const int hp = gwarp & 3;
    const int hs = lane >> 4;       // which head of the pair
    const int li = lane & 15;       // channel-pair index == point index
    const int h  = hp * 2 + hs;
    const int base = lane & 16;     // half-warp base for shuffles

    // ---- inline softmax over 16 points (half-warp shuffles stay in-half) ----
    float logit = logits[(size_t)q * 128 + h * 16 + li];
    float mx = logit;
    #pragma unroll
    for (int o = 8; o; o >>= 1) mx = fmaxf(mx, __shfl_xor_sync(0xffffffffu, mx, o));
    float e = __expf(logit - mx);
    float s = e;
    #pragma unroll
    for (int o = 8; o; o >>= 1) s += __shfl_xor_sync(0xffffffffu, s, o);
    float w = e / s;                // weight of point li, head h

    // per-lane point offsets (point li): off layout h*32 + pt*2 + xy
    const float* offq = off + (size_t)q * 256 + h * 32;
    float oxl = offq[2 * li];
    float oyl = offq[2 * li + 1];

    const __half2* vh = v + h * 16 + li;   // stride per key = 128 half2

    float2 acc = make_float2(0.f, 0.f);
    #pragma unroll
    for (int lvl = 0; lvl < NL; lvl++) {
        const int HW = c_HW[lvl];
        const int start = c_start[lvl];
        const float fHW = (float)HW;
        const float rx = ref[(size_t)q * 8 + lvl * 2 + 0];
        const float ry = ref[(size_t)q * 8 + lvl * 2 + 1];
        #pragma unroll
        for (int p = 0; p < NP; p++) {
            const int pt = lvl * 4 + p;
            float ox = __shfl_sync(0xffffffffu, oxl, base | pt);
            float oy = __shfl_sync(0xffffffffu, oyl, base | pt);
            float aw = __shfl_sync(0xffffffffu, w,   base | pt);
            float gx = fmaf(rx, fHW, ox - 0.5f);
            float gy = fmaf(ry, fHW, oy - 0.5f);
            float x0f = floorf(gx), y0f = floorf(gy);
            float wx = gx - x0f, wy = gy - y0f;
            int x0 = (int)x0f, y0 = (int)y0f;
            bool vx0 = (unsigned)x0       < (unsigned)HW;
            bool vx1 = (unsigned)(x0 + 1) < (unsigned)HW;
            float s0 = aw * (1.f - wy), s1 = aw * wy;

            if ((unsigned)y0 < (unsigned)HW) {
                int rowk = start + y0 * HW;
                if (vx0) {
                    float2 f = __half22float2(vh[(size_t)(rowk + x0) * 128]);
                    float c = s0 * (1.f - wx);
                    acc.x = fmaf(c, f.x, acc.x); acc.y = fmaf(c, f.y, acc.y);
                }
                if (vx1) {
                    float2 f = __half22float2(vh[(size_t)(rowk + x0 + 1) * 128]);
                    float c = s0 * wx;
                    acc.x = fmaf(c, f.x, acc.x); acc.y = fmaf(c, f.y, acc.y);
                }
            }
            if ((unsigned)(y0 + 1) < (unsigned)HW) {
                int rowk = start + (y0 + 1) * HW;
                if (vx0) {
                    float2 f = __half22float2(vh[(size_t)(rowk + x0) * 128]);
                    float c = s1 * (1.f - wx);
                    acc.x = fmaf(c, f.x, acc.x); acc.y = fmaf(c, f.y, acc.y);
                }
                if (vx1) {
                    float2 f = __half22float2(vh[(size_t)(rowk + x0 + 1) * 128]);
                    float c = s1 * wx;
                    acc.x = fmaf(c, f.x, acc.x); acc.y = fmaf(c, f.y, acc.y);
                }
            }
        }
    }
    // store: channels (2*li, 2*li+1) of head h
    float2* op = reinterpret_cast<float2*>(out + (size_t)q * 256 + h * 32) + li;
    *op = acc;
}

// ---------------- host launch ----------------
static void* sym_addr(const void* sym)
{
    void* p = nullptr;
    cudaGetSymbolAddress(&p, sym);
    return p;
}

extern "C" void kernel_launch(void* const* d_in, const int* in_sizes, int n_in,
                              void* d_out, int out_size)
{
    const float* query     = (const float*)d_in[0];
    const float* query_pos = (const float*)d_in[1];
    const float* value     = (const float*)d_in[2];
    const float* refpts    = (const float*)d_in[3];
    // d_in[4]: spatial_shapes (int32) — compile-time constants here
    const float* W_value   = (const float*)d_in[5];
    const float* b_value   = (const float*)d_in[6];
    const float* W_off     = (const float*)d_in[7];
    const float* b_off     = (const float*)d_in[8];
    const float* W_attn    = (const float*)d_in[9];
    const float* b_attn    = (const float*)d_in[10];
    const float* W_out     = (const float*)d_in[11];
    const float* b_out     = (const float*)d_in[12];
    float* out = (float*)d_out;

    __half* vh  = (__half*)sym_addr(g_vh);
    float* off  = (float*)sym_addr(g_off);
    float* attn = (float*)sym_addr(g_attn);
    float* samp = (float*)sym_addr(g_samp);

    // 1) v = value @ W_value^T + b_value  -> fp16 (sampling only consumer)
    {
        dim3 grid(256 / GBN, NQ / GBM);
        gemm128<<<grid, 256>>>(value, nullptr, W_value, b_value, nullptr,
                               nullptr, vh, 256);
    }
    // 2) offsets = (query+query_pos) @ W_off^T + b_off   (fused add)
    {
        dim3 grid(256 / GBN, NQ / GBM);
        gemm128<<<grid, 256>>>(query, query_pos, W_off, b_off, nullptr,
                               off, nullptr, 256);
    }
    // 3) attn logits = (query+query_pos) @ W_attn^T + b_attn  (N=128)
    {
        dim3 grid(128 / GBN, NQ / GBM);
        gemm128<<<grid, 256>>>(query, query_pos, W_attn, b_attn, nullptr,
                               attn, nullptr, 128);
    }
    // 4) deformable sampling (softmax fused) -> samp
    {
        int warps = NQ * 4;                      // warp per (q, head-pair)
        int blocks = (warps * 32) / 256;         // 10880, exact
        sample_kernel<<<blocks, 256>>>((const __half2*)vh, refpts, off, attn, samp);
    }
    // 5) out = samp @ W_out^T + b_out + query (residual), straight to d_out
    {
        dim3 grid(256 / GBN, NQ / GBM);
        gemm128<<<grid, 256>>>(samp, nullptr, W_out, b_out, query,
                               out, nullptr, 256);
    }
}

// round 5
// speedup vs baseline: 1.8243x; 1.6363x over previous
#include <cuda_runtime.h>
#include <cuda_fp16.h>
#include <math.h>
#include <stdint.h>

// ---------------- problem constants ----------------
#define NQ      21760          // num queries == num keys
#define EMBED   256
#define NH      8
#define HD      32
#define NL      4
#define NP      4
#define KDIM    256            // K for all GEMMs

__device__ __constant__ int c_start[NL] = {0, 16384, 20480, 21504};
__device__ __constant__ int c_HW[NL]    = {128, 64, 32, 16};   // square levels

// ---------------- scratch (device globals; no allocations allowed) --------
__device__ __half g_vh [NQ * EMBED];   // projected value in fp16 (key, h*32+d)
__device__ float  g_off [NQ * 256];    // sampling offsets (q, h*32 + pt*2 + xy)
__device__ float  g_attn[NQ * 128];    // attn logits (q, h*16 + pt)
__device__ float  g_samp[NQ * EMBED];  // sampled (q, h*32 + d)

// ---------------- TF32 tensor-core GEMM ----------------
// C[M,N] = (A (+A2)) @ W[N,K]^T + bias (+ident). M%128==0, N%128==0, K=256.
// 128x128x16 tile, 256 threads (8 warps, 4x2), warp tile 32x64 via m16n8k8.
#define BM 128
#define BN 128
#define BK 16
#define KPAD 20    // BK + 4: fragment LDS bank = (20*g + tig) % 32 -> all distinct

__device__ __forceinline__ uint32_t f2tf(float f) {
    uint32_t u;
    asm("cvt.rna.tf32.f32 %0, %1;" : "=r"(u) : "f"(f));
    return u;
}

__device__ __forceinline__ void mma_tf32(float* c, const uint32_t* a, const uint32_t* b) {
    asm volatile(
        "mma.sync.aligned.m16n8k8.row.col.f32.tf32.tf32.f32 "
        "{%0,%1,%2,%3}, {%4,%5,%6,%7}, {%8,%9}, {%0,%1,%2,%3};"
        : "+f"(c[0]), "+f"(c[1]), "+f"(c[2]), "+f"(c[3])
        : "r"(a[0]), "r"(a[1]), "r"(a[2]), "r"(a[3]), "r"(b[0]), "r"(b[1]));
}

__global__ void __launch_bounds__(256, 2) gemm_tc(
    const float* __restrict__ A, const float* __restrict__ A2,
    const float* __restrict__ W, const float* __restrict__ bias,
    const float* __restrict__ ident,
    float* __restrict__ C, __half* __restrict__ Ch, int N)
{
    __shared__ uint32_t As[BM][KPAD];
    __shared__ uint32_t Ws[BN][KPAD];

    const int tid  = threadIdx.x;
    const int bx   = blockIdx.x;       // N tile
    const int by   = blockIdx.y;       // M tile
    const int warp = tid >> 5;
    const int lane = tid & 31;
    const int g    = lane >> 2;        // group id (0..7)
    const int tig  = lane & 3;         // thread in group
    const int wm   = (warp >> 1) * 32; // warp row base in tile
    const int wn   = (warp & 1) * 64;  // warp col base in tile

    // global load mapping: thread -> one row, 8 consecutive k (2 float4)
    const int lr = tid >> 1;
    const int lk = (tid & 1) * 8;
    const float* Ap  = A + (size_t)(by * BM + lr) * KDIM + lk;
    const float* A2p = A2 ? A2 + (size_t)(by * BM + lr) * KDIM + lk : nullptr;
    const float* Wp  = W + (size_t)(bx * BN + lr) * KDIM + lk;

    float acc[2][8][4];
    #pragma unroll
    for (int i = 0; i < 2; i++)
        #pragma unroll
        for (int j = 0; j < 8; j++)
            #pragma unroll
            for (int t = 0; t < 4; t++) acc[i][j][t] = 0.f;

    // prefetch chunk 0
    float4 a40 = *reinterpret_cast<const float4*>(Ap);
    float4 a41 = *reinterpret_cast<const float4*>(Ap + 4);
    if (A2p) {
        float4 t0 = *reinterpret_cast<const float4*>(A2p);
        float4 t1 = *reinterpret_cast<const float4*>(A2p + 4);
        a40.x += t0.x; a40.y += t0.y; a40.z += t0.z; a40.w += t0.w;
        a41.x += t1.x; a41.y += t1.y; a41.z += t1.z; a41.w += t1.w;
    }
    float4 w40 = *reinterpret_cast<const float4*>(Wp);
    float4 w41 = *reinterpret_cast<const float4*>(Wp + 4);

    for (int k0 = 0; k0 < KDIM; k0 += BK) {
        // store chunk to smem (tf32-converted)
        uint4 ua0 = make_uint4(f2tf(a40.x), f2tf(a40.y), f2tf(a40.z), f2tf(a40.w));
        uint4 ua1 = make_uint4(f2tf(a41.x), f2tf(a41.y), f2tf(a41.z), f2tf(a41.w));
        uint4 uw0 = make_uint4(f2tf(w40.x), f2tf(w40.y), f2tf(w40.z), f2tf(w40.w));
        uint4 uw1 = make_uint4(f2tf(w41.x), f2tf(w41.y), f2tf(w41.z), f2tf(w41.w));
        *reinterpret_cast<uint4*>(&As[lr][lk])     = ua0;
        *reinterpret_cast<uint4*>(&As[lr][lk + 4]) = ua1;
        *reinterpret_cast<uint4*>(&Ws[lr][lk])     = uw0;
        *reinterpret_cast<uint4*>(&Ws[lr][lk + 4]) = uw1;
        __syncthreads();

        // prefetch next chunk
        if (k0 + BK < KDIM) {
            a40 = *reinterpret_cast<const float4*>(Ap + k0 + BK);
            a41 = *reinterpret_cast<const float4*>(Ap + k0 + BK + 4);
            if (A2p) {
                float4 t0 = *reinterpret_cast<const float4*>(A2p + k0 + BK);
                float4 t1 = *reinterpret_cast<const float4*>(A2p + k0 + BK + 4);
                a40.x += t0.x; a40.y += t0.y; a40.z += t0.z; a40.w += t0.w;
                a41.x += t1.x; a41.y += t1.y; a41.z += t1.z; a41.w += t1.w;
            }
            w40 = *reinterpret_cast<const float4*>(Wp + k0 + BK);
            w41 = *reinterpret_cast<const float4*>(Wp + k0 + BK + 4);
        }

        // 2 k-steps of 8
        #pragma unroll
        for (int kk = 0; kk < BK; kk += 8) {
            uint32_t af[2][4], bf[8][2];
            #pragma unroll
            for (int mf = 0; mf < 2; mf++) {
                int r = wm + mf * 16 + g;
                af[mf][0] = As[r][kk + tig];
                af[mf][1] = As[r + 8][kk + tig];
                af[mf][2] = As[r][kk + tig + 4];
                af[mf][3] = As[r + 8][kk + tig + 4];
            }
            #pragma unroll
            for (int nf = 0; nf < 8; nf++) {
                int n = wn + nf * 8 + g;
                bf[nf][0] = Ws[n][kk + tig];
                bf[nf][1] = Ws[n][kk + tig + 4];
            }
            #pragma unroll
            for (int mf = 0; mf < 2; mf++)
                #pragma unroll
                for (int nf = 0; nf < 8; nf++)
                    mma_tf32(acc[mf][nf], af[mf], bf[nf]);
        }
        __syncthreads();
    }

    // ---------------- epilogue ----------------
    const int nb = bx * BN + wn;
    #pragma unroll
    for (int mf = 0; mf < 2; mf++) {
        #pragma unroll
        for (int hh = 0; hh < 2; hh++) {
            int m = by * BM + wm + mf * 16 + g + hh * 8;
            #pragma unroll
            for (int nf = 0; nf < 8; nf++) {
                int col = nb + nf * 8 + tig * 2;
                float2 bb = *reinterpret_cast<const float2*>(bias + col);
                float2 r;
                r.x = acc[mf][nf][hh * 2 + 0] + bb.x;
                r.y = acc[mf][nf][hh * 2 + 1] + bb.y;
                if (ident) {
                    float2 iv = *reinterpret_cast<const float2*>(ident + (size_t)m * N + col);
                    r.x += iv.x; r.y += iv.y;
                }
                if (Ch) {
                    *reinterpret_cast<__half2*>(Ch + (size_t)m * N + col) =
                        __floats2half2_rn(r.x, r.y);
                } else {
                    *reinterpret_cast<float2*>(C + (size_t)m * N + col) = r;
                }
            }
        }
    }
}

// ---------------- deformable sampling + fused softmax ----------------
// warp per (q, head-pair); half-warp per head: 16 lanes x half2 = 32 channels.
// lane li (0..15) also owns point li for the inline 16-wide softmax.
__global__ void __launch_bounds__(256) sample_kernel(
    const __half2* __restrict__ v, const float* __restrict__ ref,
    const float* __restrict__ off, const float* __restrict__ logits,
    float* __restrict__ out)
{
    const int gwarp = (blockIdx.x * blockDim.x + threadIdx.x) >> 5;
    const int lane = threadIdx.x & 31;
    if (gwarp >= NQ * 4) return;
    const int q  = gwarp >> 2;
    const int hp = gwarp & 3;
    const int hs = lane >> 4;       // which head of the pair
    const int li = lane & 15;       // channel-pair index == point index
    const int h  = hp * 2 + hs;
    const int base = lane & 16;     // half-warp base for shuffles

    // ---- inline softmax over 16 points (half-warp shuffles stay in-half) ----
    float logit = logits[(size_t)q * 128 + h * 16 + li];
    float mx = logit;
    #pragma unroll
    for (int o = 8; o; o >>= 1) mx = fmaxf(mx, __shfl_xor_sync(0xffffffffu, mx, o));
    float e = __expf(logit - mx);
    float s = e;
    #pragma unroll
    for (int o = 8; o; o >>= 1) s += __shfl_xor_sync(0xffffffffu, s, o);
    float w = e / s;                // weight of point li, head h

    // per-lane point offsets (point li): off layout h*32 + pt*2 + xy
    const float* offq = off + (size_t)q * 256 + h * 32;
    float oxl = offq[2 * li];
    float oyl = offq[2 * li + 1];

    const __half2* vh = v + h * 16 + li;   // stride per key = 128 half2

    float2 acc = make_float2(0.f, 0.f);
    #pragma unroll
    for (int lvl = 0; lvl < NL; lvl++) {
        const int HW = c_HW[lvl];
        const int start = c_start[lvl];
        const float fHW = (float)HW;
        const float rx = ref[(size_t)q * 8 + lvl * 2 + 0];
        const float ry = ref[(size_t)q * 8 + lvl * 2 + 1];
        #pragma unroll
        for (int p = 0; p < NP; p++) {
            const int pt = lvl * 4 + p;
            float ox = __shfl_sync(0xffffffffu, oxl, base | pt);
            float oy = __shfl_sync(0xffffffffu, oyl, base | pt);
            float aw = __shfl_sync(0xffffffffu, w,   base | pt);
            float gx = fmaf(rx, fHW, ox - 0.5f);
            float gy = fmaf(ry, fHW, oy - 0.5f);
            float x0f = floorf(gx), y0f = floorf(gy);
            float wx = gx - x0f, wy = gy - y0f;
            int x0 = (int)x0f, y0 = (int)y0f;
            bool vx0 = (unsigned)x0       < (unsigned)HW;
            bool vx1 = (unsigned)(x0 + 1) < (unsigned)HW;
            float s0 = aw * (1.f - wy), s1 = aw * wy;

            if ((unsigned)y0 < (unsigned)HW) {
                int rowk = start + y0 * HW;
                if (vx0) {
                    float2 f = __half22float2(vh[(size_t)(rowk + x0) * 128]);
                    float c = s0 * (1.f - wx);
                    acc.x = fmaf(c, f.x, acc.x); acc.y = fmaf(c, f.y, acc.y);
                }
                if (vx1) {
                    float2 f = __half22float2(vh[(size_t)(rowk + x0 + 1) * 128]);
                    float c = s0 * wx;
                    acc.x = fmaf(c, f.x, acc.x); acc.y = fmaf(c, f.y, acc.y);
                }
            }
            if ((unsigned)(y0 + 1) < (unsigned)HW) {
                int rowk = start + (y0 + 1) * HW;
                if (vx0) {
                    float2 f = __half22float2(vh[(size_t)(rowk + x0) * 128]);
                    float c = s1 * (1.f - wx);
                    acc.x = fmaf(c, f.x, acc.x); acc.y = fmaf(c, f.y, acc.y);
                }
                if (vx1) {
                    float2 f = __half22float2(vh[(size_t)(rowk + x0 + 1) * 128]);
                    float c = s1 * wx;
                    acc.x = fmaf(c, f.x, acc.x); acc.y = fmaf(c, f.y, acc.y);
                }
            }
        }
    }
    // store: channels (2*li, 2*li+1) of head h
    float2* op = reinterpret_cast<float2*>(out + (size_t)q * 256 + h * 32) + li;
    *op = acc;
}

// ---------------- host launch ----------------
static void* sym_addr(const void* sym)
{
    void* p = nullptr;
    cudaGetSymbolAddress(&p, sym);
    return p;
}

extern "C" void kernel_launch(void* const* d_in, const int* in_sizes, int n_in,
                              void* d_out, int out_size)
{
    const float* query     = (const float*)d_in[0];
    const float* query_pos = (const float*)d_in[1];
    const float* value     = (const float*)d_in[2];
    const float* refpts    = (const float*)d_in[3];
    // d_in[4]: spatial_shapes (int32) — compile-time constants here
    const float* W_value   = (const float*)d_in[5];
    const float* b_value   = (const float*)d_in[6];
    const float* W_off     = (const float*)d_in[7];
    const float* b_off     = (const float*)d_in[8];
    const float* W_attn    = (const float*)d_in[9];
    const float* b_attn    = (const float*)d_in[10];
    const float* W_out     = (const float*)d_in[11];
    const float* b_out     = (const float*)d_in[12];
    float* out = (float*)d_out;

    __half* vh  = (__half*)sym_addr(g_vh);
    float* off  = (float*)sym_addr(g_off);
    float* attn = (float*)sym_addr(g_attn);
    float* samp = (float*)sym_addr(g_samp);

    // 1) v = value @ W_value^T + b_value  -> fp16 (sampling only consumer)
    {
        dim3 grid(256 / BN, NQ / BM);
        gemm_tc<<<grid, 256>>>(value, nullptr, W_value, b_value, nullptr,
                               nullptr, vh, 256);
    }
    // 2) offsets = (query+query_pos) @ W_off^T + b_off   (fused add)
    {
        dim3 grid(256 / BN, NQ / BM);
        gemm_tc<<<grid, 256>>>(query, query_pos, W_off, b_off, nullptr,
                               off, nullptr, 256);
    }
    // 3) attn logits = (query+query_pos) @ W_attn^T + b_attn  (N=128)
    {
        dim3 grid(128 / BN, NQ / BM);
        gemm_tc<<<grid, 256>>>(query, query_pos, W_attn, b_attn, nullptr,
                               attn, nullptr, 128);
    }
    // 4) deformable sampling (softmax fused) -> samp
    {
        int warps = NQ * 4;                      // warp per (q, head-pair)
        int blocks = (warps * 32) / 256;         // 10880, exact
        sample_kernel<<<blocks, 256>>>((const __half2*)vh, refpts, off, attn, samp);
    }
    // 5) out = samp @ W_out^T + b_out + query (residual), straight to d_out
    {
        dim3 grid(256 / BN, NQ / BM);
        gemm_tc<<<grid, 256>>>(samp, nullptr, W_out, b_out, query,
                               out, nullptr, 256);
    }
}

// round 6
// speedup vs baseline: 2.0789x; 1.1396x over previous
#include <cuda_runtime.h>
#include <cuda_fp16.h>
#include <math.h>
#include <stdint.h>

// ---------------- problem constants ----------------
#define NQ      21760          // num queries == num keys
#define EMBED   256
#define NH      8
#define NL      4
#define NP      4
#define KDIM    256            // K for all GEMMs

__device__ __constant__ int c_start[NL] = {0, 16384, 20480, 21504};
__device__ __constant__ int c_HW[NL]    = {128, 64, 32, 16};   // square levels

// ---------------- scratch (device globals; no allocations allowed) --------
__device__ __half g_vh [NQ * EMBED];   // projected value fp16 (key, h*32+d)
__device__ float  g_off [NQ * 256];    // offsets (q, h*32 + pt*2 + xy)
__device__ float  g_attn[NQ * 128];    // attn logits (q, h*16 + pt)
__device__ float  g_samp[NQ * EMBED];  // sampled (q, h*32 + d)

// ---------------- fp16 tensor-core GEMM (HMMA m16n8k16 + ldmatrix) --------
// C[M,N] = (A (+A2)) @ W[N,K]^T + bias (+ident). M%128==0, N%128==0, K=256.
// 128x128 tile, BK=32, 256 threads (8 warps 4x2, warp tile 32x64).
#define BM 128
#define BN 128
#define BK 32
#define PITCH 40   // halves per smem row; 8-row step = 20 words -> all banks distinct

__device__ __forceinline__ uint32_t pack2(float x, float y) {
    __half2 h = __floats2half2_rn(x, y);
    return *reinterpret_cast<uint32_t*>(&h);
}

__device__ __forceinline__ void ldsm_x4(uint32_t* r, const __half* p) {
    uint32_t a = (uint32_t)__cvta_generic_to_shared(p);
    asm volatile("ldmatrix.sync.aligned.m8n8.x4.shared.b16 {%0,%1,%2,%3}, [%4];"
                 : "=r"(r[0]), "=r"(r[1]), "=r"(r[2]), "=r"(r[3]) : "r"(a));
}

__device__ __forceinline__ void mma_f16(float* c, const uint32_t* a,
                                        uint32_t b0, uint32_t b1) {
    asm volatile(
        "mma.sync.aligned.m16n8k16.row.col.f32.f16.f16.f32 "
        "{%0,%1,%2,%3}, {%4,%5,%6,%7}, {%8,%9}, {%0,%1,%2,%3};"
        : "+f"(c[0]), "+f"(c[1]), "+f"(c[2]), "+f"(c[3])
        : "r"(a[0]), "r"(a[1]), "r"(a[2]), "r"(a[3]), "r"(b0), "r"(b1));
}

__global__ void __launch_bounds__(256, 2) gemm_hmma(
    const float* __restrict__ A, const float* __restrict__ A2,
    const float* __restrict__ W, const float* __restrict__ bias,
    const float* __restrict__ ident,
    float* __restrict__ C, __half* __restrict__ Ch, int N)
{
    __shared__ __half As[2][BM][PITCH];
    __shared__ __half Ws[2][BN][PITCH];

    const int tid  = threadIdx.x;
    const int bx   = blockIdx.x;       // N tile
    const int by   = blockIdx.y;       // M tile
    const int warp = tid >> 5;
    const int lane = tid & 31;
    const int g    = lane >> 2;
    const int tig  = lane & 3;
    const int wm   = (warp >> 1) * 32;
    const int wn   = (warp & 1) * 64;

    // loader: thread t -> one row (A row t, or W row t-128), 32 k per chunk
    const bool isA = tid < 128;
    const int lrow = isA ? tid : tid - 128;
    const float* src  = isA ? A + (size_t)(by * BM + lrow) * KDIM
                            : W + (size_t)(bx * BN + lrow) * KDIM;
    const float* src2 = (isA && A2) ? A2 + (size_t)(by * BM + lrow) * KDIM : nullptr;

    uint4 pf[2];   // 32 half = 2 x (8 half2) ... actually 32 half = 4 uint4
    uint4 pf2[2];

    auto load_chunk = [&](int k0) {
        #pragma unroll
        for (int i = 0; i < 2; i++) {
            float4 x0 = *reinterpret_cast<const float4*>(src + k0 + i * 16);
            float4 x1 = *reinterpret_cast<const float4*>(src + k0 + i * 16 + 4);
            float4 x2 = *reinterpret_cast<const float4*>(src + k0 + i * 16 + 8);
            float4 x3 = *reinterpret_cast<const float4*>(src + k0 + i * 16 + 12);
            if (src2) {
                float4 y0 = *reinterpret_cast<const float4*>(src2 + k0 + i * 16);
                float4 y1 = *reinterpret_cast<const float4*>(src2 + k0 + i * 16 + 4);
                float4 y2 = *reinterpret_cast<const float4*>(src2 + k0 + i * 16 + 8);
                float4 y3 = *reinterpret_cast<const float4*>(src2 + k0 + i * 16 + 12);
                x0.x+=y0.x; x0.y+=y0.y; x0.z+=y0.z; x0.w+=y0.w;
                x1.x+=y1.x; x1.y+=y1.y; x1.z+=y1.z; x1.w+=y1.w;
                x2.x+=y2.x; x2.y+=y2.y; x2.z+=y2.z; x2.w+=y2.w;
                x3.x+=y3.x; x3.y+=y3.y; x3.z+=y3.z; x3.w+=y3.w;
            }
            pf[i]  = make_uint4(pack2(x0.x,x0.y), pack2(x0.z,x0.w),
                                pack2(x1.x,x1.y), pack2(x1.z,x1.w));
            pf2[i] = make_uint4(pack2(x2.x,x2.y), pack2(x2.z,x2.w),
                                pack2(x3.x,x3.y), pack2(x3.z,x3.w));
        }
    };
    auto store_chunk = [&](int buf) {
        __half* dst = isA ? &As[buf][lrow][0] : &Ws[buf][lrow][0];
        *reinterpret_cast<uint4*>(dst)      = pf[0];
        *reinterpret_cast<uint4*>(dst + 8)  = pf2[0];
        *reinterpret_cast<uint4*>(dst + 16) = pf[1];
        *reinterpret_cast<uint4*>(dst + 24) = pf2[1];
    };

    float acc[2][8][4];
    #pragma unroll
    for (int i = 0; i < 2; i++)
        #pragma unroll
        for (int j = 0; j < 8; j++)
            #pragma unroll
            for (int t = 0; t < 4; t++) acc[i][j][t] = 0.f;

    load_chunk(0);

    const int lrow16 = lane & 15;
    const int lk8    = (lane >> 4) << 3;

    #pragma unroll
    for (int c = 0; c < KDIM / BK; c++) {     // 8 chunks
        const int buf = c & 1;
        store_chunk(buf);
        __syncthreads();
        if (c < KDIM / BK - 1) load_chunk((c + 1) * BK);

        #pragma unroll
        for (int kk = 0; kk < BK; kk += 16) {
            uint32_t af[2][4];
            #pragma unroll
            for (int mf = 0; mf < 2; mf++)
                ldsm_x4(af[mf], &As[buf][wm + mf * 16 + lrow16][kk + lk8]);
            uint32_t bf[8][2];
            #pragma unroll
            for (int npg = 0; npg < 4; npg++) {
                uint32_t r[4];
                ldsm_x4(r, &Ws[buf][wn + npg * 16 + lrow16][kk + lk8]);
                bf[npg * 2 + 0][0] = r[0]; bf[npg * 2 + 0][1] = r[2];
                bf[npg * 2 + 1][0] = r[1]; bf[npg * 2 + 1][1] = r[3];
            }
            #pragma unroll
            for (int mf = 0; mf < 2; mf++)
                #pragma unroll
                for (int nf = 0; nf < 8; nf++)
                    mma_f16(acc[mf][nf], af[mf], bf[nf][0], bf[nf][1]);
        }
        // next iteration's store targets buf^1; its last readers synced above
    }

    // ---------------- epilogue ----------------
    const int nb = bx * BN + wn;
    #pragma unroll
    for (int mf = 0; mf < 2; mf++) {
        #pragma unroll
        for (int hh = 0; hh < 2; hh++) {
            int m = by * BM + wm + mf * 16 + g + hh * 8;
            #pragma unroll
            for (int nf = 0; nf < 8; nf++) {
                int col = nb + nf * 8 + tig * 2;
                float2 bb = *reinterpret_cast<const float2*>(bias + col);
                float2 r;
                r.x = acc[mf][nf][hh * 2 + 0] + bb.x;
                r.y = acc[mf][nf][hh * 2 + 1] + bb.y;
                if (ident) {
                    float2 iv = *reinterpret_cast<const float2*>(
                        ident + (size_t)m * N + col);
                    r.x += iv.x; r.y += iv.y;
                }
                if (Ch) {
                    *reinterpret_cast<__half2*>(Ch + (size_t)m * N + col) =
                        __floats2half2_rn(r.x, r.y);
                } else {
                    *reinterpret_cast<float2*>(C + (size_t)m * N + col) = r;
                }
            }
        }
    }
}

// ---------------- deformable sampling + fused softmax ----------------
// warp per (q, head-quad): 8 lanes per head, lane = 4 channels (uint2 gather).
// lane li (0..7) owns points 2li, 2li+1 for the inline softmax/offsets.
__global__ void __launch_bounds__(256) sample_kernel(
    const uint2* __restrict__ v, const float* __restrict__ ref,
    const float4* __restrict__ off4, const float2* __restrict__ lg2,
    float4* __restrict__ out)
{
    const int gwarp = (blockIdx.x * blockDim.x + threadIdx.x) >> 5;
    const int lane = threadIdx.x & 31;
    if (gwarp >= NQ * 2) return;
    const int q  = gwarp >> 1;
    const int hq = gwarp & 1;
    const int hs = lane >> 3;        // head within quad
    const int li = lane & 7;
    const int h  = hq * 4 + hs;
    const int gbase = lane & 24;     // 8-lane group base

    // ---- softmax over 16 points: lane holds logits 2li, 2li+1 ----
    float2 lg = lg2[(size_t)q * 64 + h * 8 + li];
    float m = fmaxf(lg.x, lg.y);
    #pragma unroll
    for (int o = 4; o; o >>= 1) m = fmaxf(m, __shfl_xor_sync(0xffffffffu, m, o));
    float e0 = __expf(lg.x - m), e1 = __expf(lg.y - m);
    float s = e0 + e1;
    #pragma unroll
    for (int o = 4; o; o >>= 1) s += __shfl_xor_sync(0xffffffffu, s, o);
    float inv = 1.f / s;
    float w0 = e0 * inv, w1 = e1 * inv;

    // offsets for points 2li, 2li+1: (ox0, oy0, ox1, oy1)
    float4 o4 = off4[(size_t)q * 64 + h * 8 + li];

    const uint2* vq = v + h * 8 + li;      // + key * 64

    float4 acc = make_float4(0.f, 0.f, 0.f, 0.f);
    #pragma unroll
    for (int lvl = 0; lvl < NL; lvl++) {
        const int HW = c_HW[lvl];
        const int start = c_start[lvl];
        const float fHW = (float)HW;
        const float rx = ref[(size_t)q * 8 + lvl * 2 + 0];
        const float ry = ref[(size_t)q * 8 + lvl * 2 + 1];
        #pragma unroll
        for (int p = 0; p < NP; p++) {
            const int pt = lvl * 4 + p;              // compile-time
            const int owner = gbase | (pt >> 1);
            float ox = __shfl_sync(0xffffffffu, (pt & 1) ? o4.z : o4.x, owner);
            float oy = __shfl_sync(0xffffffffu, (pt & 1) ? o4.w : o4.y, owner);
            float aw = __shfl_sync(0xffffffffu, (pt & 1) ? w1 : w0, owner);

            float gx = fmaf(rx, fHW, ox - 0.5f);
            float gy = fmaf(ry, fHW, oy - 0.5f);
            float x0f = floorf(gx), y0f = floorf(gy);
            float wx = gx - x0f, wy = gy - y0f;
            int x0 = (int)x0f, y0 = (int)y0f;
            bool vx0 = (unsigned)x0       < (unsigned)HW;
            bool vx1 = (unsigned)(x0 + 1) < (unsigned)HW;
            float s0 = aw * (1.f - wy), s1 = aw * wy;

            if ((unsigned)y0 < (unsigned)HW) {
                int rowk = start + y0 * HW;
                if (vx0) {
                    uint2 u = vq[(size_t)(rowk + x0) * 64];
                    float2 f0 = __half22float2(*reinterpret_cast<__half2*>(&u.x));
                    float2 f1 = __half22float2(*reinterpret_cast<__half2*>(&u.y));
                    float cc = s0 * (1.f - wx);
                    acc.x = fmaf(cc, f0.x, acc.x); acc.y = fmaf(cc, f0.y, acc.y);
                    acc.z = fmaf(cc, f1.x, acc.z); acc.w = fmaf(cc, f1.y, acc.w);
                }
                if (vx1) {
                    uint2 u = vq[(size_t)(rowk + x0 + 1) * 64];
                    float2 f0 = __half22float2(*reinterpret_cast<__half2*>(&u.x));
                    float2 f1 = __half22float2(*reinterpret_cast<__half2*>(&u.y));
                    float cc = s0 * wx;
                    acc.x = fmaf(cc, f0.x, acc.x); acc.y = fmaf(cc, f0.y, acc.y);
                    acc.z = fmaf(cc, f1.x, acc.z); acc.w = fmaf(cc, f1.y, acc.w);
                }
            }
            if ((unsigned)(y0 + 1) < (unsigned)HW) {
                int rowk = start + (y0 + 1) * HW;
                if (vx0) {
                    uint2 u = vq[(size_t)(rowk + x0) * 64];
                    float2 f0 = __half22float2(*reinterpret_cast<__half2*>(&u.x));
                    float2 f1 = __half22float2(*reinterpret_cast<__half2*>(&u.y));
                    float cc = s1 * (1.f - wx);
                    acc.x = fmaf(cc, f0.x, acc.x); acc.y = fmaf(cc, f0.y, acc.y);
                    acc.z = fmaf(cc, f1.x, acc.z); acc.w = fmaf(cc, f1.y, acc.w);
                }
                if (vx1) {
                    uint2 u = vq[(size_t)(rowk + x0 + 1) * 64];
                    float2 f0 = __half22float2(*reinterpret_cast<__half2*>(&u.x));
                    float2 f1 = __half22float2(*reinterpret_cast<__half2*>(&u.y));
                    float cc = s1 * wx;
                    acc.x = fmaf(cc, f0.x, acc.x); acc.y = fmaf(cc, f0.y, acc.y);
                    acc.z = fmaf(cc, f1.x, acc.z); acc.w = fmaf(cc, f1.y, acc.w);
                }
            }
        }
    }
    // store channels 4li..4li+3 of head h
    out[(size_t)q * 64 + h * 8 + li] = acc;
}

// ---------------- host launch ----------------
static void* sym_addr(const void* sym)
{
    void* p = nullptr;
    cudaGetSymbolAddress(&p, sym);
    return p;
}

extern "C" void kernel_launch(void* const* d_in, const int* in_sizes, int n_in,
                              void* d_out, int out_size)
{
    const float* query     = (const float*)d_in[0];
    const float* query_pos = (const float*)d_in[1];
    const float* value     = (const float*)d_in[2];
    const float* refpts    = (const float*)d_in[3];
    // d_in[4]: spatial_shapes (int32) — compile-time constants here
    const float* W_value   = (const float*)d_in[5];
    const float* b_value   = (const float*)d_in[6];
    const float* W_off     = (const float*)d_in[7];
    const float* b_off     = (const float*)d_in[8];
    const float* W_attn    = (const float*)d_in[9];
    const float* b_attn    = (const float*)d_in[10];
    const float* W_out     = (const float*)d_in[11];
    const float* b_out     = (const float*)d_in[12];
    float* out = (float*)d_out;

    __half* vh  = (__half*)sym_addr(g_vh);
    float* off  = (float*)sym_addr(g_off);
    float* attn = (float*)sym_addr(g_attn);
    float* samp = (float*)sym_addr(g_samp);

    // 1) v = value @ W_value^T + b_value  -> fp16 (sampling only consumer)
    {
        dim3 grid(256 / BN, NQ / BM);
        gemm_hmma<<<grid, 256>>>(value, nullptr, W_value, b_value, nullptr,
                                 nullptr, vh, 256);
    }
    // 2) offsets = (query+query_pos) @ W_off^T + b_off   (fused add)
    {
        dim3 grid(256 / BN, NQ / BM);
        gemm_hmma<<<grid, 256>>>(query, query_pos, W_off, b_off, nullptr,
                                 off, nullptr, 256);
    }
    // 3) attn logits = (query+query_pos) @ W_attn^T + b_attn  (N=128)
    {
        dim3 grid(128 / BN, NQ / BM);
        gemm_hmma<<<grid, 256>>>(query, query_pos, W_attn, b_attn, nullptr,
                                 attn, nullptr, 128);
    }
    // 4) deformable sampling (softmax fused) -> samp
    {
        int warps = NQ * 2;                      // warp per (q, head-quad)
        int blocks = (warps * 32) / 256;         // 5440, exact
        sample_kernel<<<blocks, 256>>>((const uint2*)vh, refpts,
                                       (const float4*)off, (const float2*)attn,
                                       (float4*)samp);
    }
    // 5) out = samp @ W_out^T + b_out + query (residual), straight to d_out
    {
        dim3 grid(256 / BN, NQ / BM);
        gemm_hmma<<<grid, 256>>>(samp, nullptr, W_out, b_out, query,
                                 out, nullptr, 256);
    }
}

// round 7
// speedup vs baseline: 3.2508x; 1.5637x over previous
#include <cuda_runtime.h>
#include <cuda_fp16.h>
#include <math.h>
#include <stdint.h>

// ---------------- problem constants ----------------
#define NQ      21760          // num queries == num keys
#define EMBED   256
#define NH      8
#define NL      4
#define NP      4
#define KDIM    256            // K for all GEMMs

__device__ __constant__ int c_start[NL] = {0, 16384, 20480, 21504};
__device__ __constant__ int c_HW[NL]    = {128, 64, 32, 16};   // square levels

// ---------------- scratch (device globals; no allocations allowed) --------
__device__ __half g_vh  [NQ * EMBED];  // projected value fp16 (key, h*32+d)
__device__ float  g_oa  [NQ * 384];    // [offsets(256) | attn logits(128)] per q
__device__ float  g_samp[NQ * EMBED];  // sampled (q, h*32 + d)
__device__ float  g_wcat[384 * 256];   // concat W_off;W_attn
__device__ float  g_bcat[384];         // concat b_off;b_attn

// ---------------- prep: concatenate W_off/W_attn and biases ----------------
__global__ void __launch_bounds__(256) prep_cat(
    const float* __restrict__ Woff, const float* __restrict__ boff,
    const float* __restrict__ Wattn, const float* __restrict__ battn,
    float* __restrict__ Wcat, float* __restrict__ bcat)
{
    int i = blockIdx.x * blockDim.x + threadIdx.x;
    if (i < 256 * 256) Wcat[i] = Woff[i];
    else if (i < 384 * 256) Wcat[i] = Wattn[i - 256 * 256];
    if (i < 256) bcat[i] = boff[i];
    else if (i < 384) bcat[i] = battn[i - 256];
}

// ---------------- fp16 tensor-core GEMM (HMMA m16n8k16 + ldmatrix) --------
// C[M,N] = (A (+A2)) @ W[N,K]^T + bias (+ident). M%128==0, N%128==0, K=256.
// 128x128 tile, BK=32, 256 threads (8 warps 4x2, warp tile 32x64).
// COALESCED loader: 8 lanes cover one contiguous 128B row-chunk.
#define BM 128
#define BN 128
#define BK 32
#define PITCH 40   // halves per smem row; 8-row LDSM phases hit distinct banks

__device__ __forceinline__ uint32_t pack2(float x, float y) {
    __half2 h = __floats2half2_rn(x, y);
    return *reinterpret_cast<uint32_t*>(&h);
}

__device__ __forceinline__ void ldsm_x4(uint32_t* r, const __half* p) {
    uint32_t a = (uint32_t)__cvta_generic_to_shared(p);
    asm volatile("ldmatrix.sync.aligned.m8n8.x4.shared.b16 {%0,%1,%2,%3}, [%4];"
                 : "=r"(r[0]), "=r"(r[1]), "=r"(r[2]), "=r"(r[3]) : "r"(a));
}

__device__ __forceinline__ void mma_f16(float* c, const uint32_t* a,
                                        uint32_t b0, uint32_t b1) {
    asm volatile(
        "mma.sync.aligned.m16n8k16.row.col.f32.f16.f16.f32 "
        "{%0,%1,%2,%3}, {%4,%5,%6,%7}, {%8,%9}, {%0,%1,%2,%3};"
        : "+f"(c[0]), "+f"(c[1]), "+f"(c[2]), "+f"(c[3])
        : "r"(a[0]), "r"(a[1]), "r"(a[2]), "r"(a[3]), "r"(b0), "r"(b1));
}

__global__ void __launch_bounds__(256, 2) gemm_hmma(
    const float* __restrict__ A, const float* __restrict__ A2,
    const float* __restrict__ W, const float* __restrict__ bias,
    const float* __restrict__ ident,
    float* __restrict__ C, __half* __restrict__ Ch, int N)
{
    __shared__ __half As[2][BM][PITCH];
    __shared__ __half Ws[2][BN][PITCH];

    const int tid  = threadIdx.x;
    const int bx   = blockIdx.x;       // N tile
    const int by   = blockIdx.y;       // M tile
    const int warp = tid >> 5;
    const int lane = tid & 31;
    const int g    = lane >> 2;
    const int tig  = lane & 3;
    const int wm   = (warp >> 1) * 32;
    const int wn   = (warp & 1) * 64;

    // coalesced loader: pass p covers 32 virtual rows; 8 lanes span one
    // row's 32-float (128B) chunk. passes 0-3 -> A rows, 4-7 -> W rows.
    const int lrow8 = tid >> 3;        // 0..31
    const int kq    = tid & 7;         // float4 slot within chunk
    const float* arow = A + (size_t)(by * BM + lrow8) * KDIM + kq * 4;
    const float* a2row = A2 ? A2 + (size_t)(by * BM + lrow8) * KDIM + kq * 4 : nullptr;
    const float* wrow = W + (size_t)(bx * BN + lrow8) * KDIM + kq * 4;

    uint2 pfh[8];

    auto load_chunk = [&](int k0) {
        #pragma unroll
        for (int pass = 0; pass < 4; pass++) {
            float4 x = *reinterpret_cast<const float4*>(arow + (size_t)pass * 32 * KDIM + k0);
            if (a2row) {
                float4 y = *reinterpret_cast<const float4*>(a2row + (size_t)pass * 32 * KDIM + k0);
                x.x += y.x; x.y += y.y; x.z += y.z; x.w += y.w;
            }
            pfh[pass] = make_uint2(pack2(x.x, x.y), pack2(x.z, x.w));
        }
        #pragma unroll
        for (int pass = 0; pass < 4; pass++) {
            float4 x = *reinterpret_cast<const float4*>(wrow + (size_t)pass * 32 * KDIM + k0);
            pfh[4 + pass] = make_uint2(pack2(x.x, x.y), pack2(x.z, x.w));
        }
    };
    auto store_chunk = [&](int buf) {
        #pragma unroll
        for (int pass = 0; pass < 4; pass++)
            *reinterpret_cast<uint2*>(&As[buf][pass * 32 + lrow8][kq * 4]) = pfh[pass];
        #pragma unroll
        for (int pass = 0; pass < 4; pass++)
            *reinterpret_cast<uint2*>(&Ws[buf][pass * 32 + lrow8][kq * 4]) = pfh[4 + pass];
    };

    float acc[2][8][4];
    #pragma unroll
    for (int i = 0; i < 2; i++)
        #pragma unroll
        for (int j = 0; j < 8; j++)
            #pragma unroll
            for (int t = 0; t < 4; t++) acc[i][j][t] = 0.f;

    load_chunk(0);

    const int lrow16 = lane & 15;
    const int lk8    = (lane >> 4) << 3;

    #pragma unroll
    for (int c = 0; c < KDIM / BK; c++) {     // 8 chunks
        const int buf = c & 1;
        store_chunk(buf);
        __syncthreads();
        if (c < KDIM / BK - 1) load_chunk((c + 1) * BK);

        #pragma unroll
        for (int kk = 0; kk < BK; kk += 16) {
            uint32_t af[2][4];
            #pragma unroll
            for (int mf = 0; mf < 2; mf++)
                ldsm_x4(af[mf], &As[buf][wm + mf * 16 + lrow16][kk + lk8]);
            uint32_t bf[8][2];
            #pragma unroll
            for (int npg = 0; npg < 4; npg++) {
                uint32_t r[4];
                ldsm_x4(r, &Ws[buf][wn + npg * 16 + lrow16][kk + lk8]);
                bf[npg * 2 + 0][0] = r[0]; bf[npg * 2 + 0][1] = r[2];
                bf[npg * 2 + 1][0] = r[1]; bf[npg * 2 + 1][1] = r[3];
            }
            #pragma unroll
            for (int mf = 0; mf < 2; mf++)
                #pragma unroll
                for (int nf = 0; nf < 8; nf++)
                    mma_f16(acc[mf][nf], af[mf], bf[nf][0], bf[nf][1]);
        }
    }

    // ---------------- epilogue ----------------
    const int nb = bx * BN + wn;
    #pragma unroll
    for (int mf = 0; mf < 2; mf++) {
        #pragma unroll
        for (int hh = 0; hh < 2; hh++) {
            int m = by * BM + wm + mf * 16 + g + hh * 8;
            #pragma unroll
            for (int nf = 0; nf < 8; nf++) {
                int col = nb + nf * 8 + tig * 2;
                float2 bb = *reinterpret_cast<const float2*>(bias + col);
                float2 r;
                r.x = acc[mf][nf][hh * 2 + 0] + bb.x;
                r.y = acc[mf][nf][hh * 2 + 1] + bb.y;
                if (ident) {
                    float2 iv = *reinterpret_cast<const float2*>(
                        ident + (size_t)m * N + col);
                    r.x += iv.x; r.y += iv.y;
                }
                if (Ch) {
                    *reinterpret_cast<__half2*>(Ch + (size_t)m * N + col) =
                        __floats2half2_rn(r.x, r.y);
                } else {
                    *reinterpret_cast<float2*>(C + (size_t)m * N + col) = r;
                }
            }
        }
    }
}

// ---------------- deformable sampling + fused softmax ----------------
// warp per (q, head-quad): 8 lanes per head, lane = 4 channels (uint2 gather).
// reads offsets/logits from the combined g_oa buffer (row width 384 floats).
__global__ void __launch_bounds__(256) sample_kernel(
    const uint2* __restrict__ v, const float* __restrict__ ref,
    const float* __restrict__ oa, float4* __restrict__ out)
{
    const int gwarp = (blockIdx.x * blockDim.x + threadIdx.x) >> 5;
    const int lane = threadIdx.x & 31;
    if (gwarp >= NQ * 2) return;
    const int q  = gwarp >> 1;
    const int hq = gwarp & 1;
    const int hs = lane >> 3;        // head within quad
    const int li = lane & 7;
    const int h  = hq * 4 + hs;
    const int gbase = lane & 24;     // 8-lane group base

    // offsets for points 2li, 2li+1: (ox0, oy0, ox1, oy1); row width 96 float4
    float4 o4 = reinterpret_cast<const float4*>(oa)[(size_t)q * 96 + h * 8 + li];
    // logits 2li, 2li+1: attn starts at float 256 of the 384-wide row
    float2 lg = reinterpret_cast<const float2*>(oa)[(size_t)q * 192 + 128 + h * 8 + li];

    // ---- softmax over 16 points (8-lane groups) ----
    float m = fmaxf(lg.x, lg.y);
    #pragma unroll
    for (int o = 4; o; o >>= 1) m = fmaxf(m, __shfl_xor_sync(0xffffffffu, m, o));
    float e0 = __expf(lg.x - m), e1 = __expf(lg.y - m);
    float s = e0 + e1;
    #pragma unroll
    for (int o = 4; o; o >>= 1) s += __shfl_xor_sync(0xffffffffu, s, o);
    float inv = 1.f / s;
    float w0 = e0 * inv, w1 = e1 * inv;

    const uint2* vq = v + h * 8 + li;      // + key * 64

    float4 acc = make_float4(0.f, 0.f, 0.f, 0.f);
    #pragma unroll
    for (int lvl = 0; lvl < NL; lvl++) {
        const int HW = c_HW[lvl];
        const int start = c_start[lvl];
        const float fHW = (float)HW;
        const float rx = ref[(size_t)q * 8 + lvl * 2 + 0];
        const float ry = ref[(size_t)q * 8 + lvl * 2 + 1];
        #pragma unroll
        for (int p = 0; p < NP; p++) {
            const int pt = lvl * 4 + p;              // compile-time
            const int owner = gbase | (pt >> 1);
            float ox = __shfl_sync(0xffffffffu, (pt & 1) ? o4.z : o4.x, owner);
            float oy = __shfl_sync(0xffffffffu, (pt & 1) ? o4.w : o4.y, owner);
            float aw = __shfl_sync(0xffffffffu, (pt & 1) ? w1 : w0, owner);

            float gx = fmaf(rx, fHW, ox - 0.5f);
            float gy = fmaf(ry, fHW, oy - 0.5f);
            float x0f = floorf(gx), y0f = floorf(gy);
            float wx = gx - x0f, wy = gy - y0f;
            int x0 = (int)x0f, y0 = (int)y0f;
            bool vx0 = (unsigned)x0       < (unsigned)HW;
            bool vx1 = (unsigned)(x0 + 1) < (unsigned)HW;
            float s0 = aw * (1.f - wy), s1 = aw * wy;

            if ((unsigned)y0 < (unsigned)HW) {
                int rowk = start + y0 * HW;
                if (vx0) {
                    uint2 u = vq[(size_t)(rowk + x0) * 64];
                    float2 f0 = __half22float2(*reinterpret_cast<__half2*>(&u.x));
                    float2 f1 = __half22float2(*reinterpret_cast<__half2*>(&u.y));
                    float cc = s0 * (1.f - wx);
                    acc.x = fmaf(cc, f0.x, acc.x); acc.y = fmaf(cc, f0.y, acc.y);
                    acc.z = fmaf(cc, f1.x, acc.z); acc.w = fmaf(cc, f1.y, acc.w);
                }
                if (vx1) {
                    uint2 u = vq[(size_t)(rowk + x0 + 1) * 64];
                    float2 f0 = __half22float2(*reinterpret_cast<__half2*>(&u.x));
                    float2 f1 = __half22float2(*reinterpret_cast<__half2*>(&u.y));
                    float cc = s0 * wx;
                    acc.x = fmaf(cc, f0.x, acc.x); acc.y = fmaf(cc, f0.y, acc.y);
                    acc.z = fmaf(cc, f1.x, acc.z); acc.w = fmaf(cc, f1.y, acc.w);
                }
            }
            if ((unsigned)(y0 + 1) < (unsigned)HW) {
                int rowk = start + (y0 + 1) * HW;
                if (vx0) {
                    uint2 u = vq[(size_t)(rowk + x0) * 64];
                    float2 f0 = __half22float2(*reinterpret_cast<__half2*>(&u.x));
                    float2 f1 = __half22float2(*reinterpret_cast<__half2*>(&u.y));
                    float cc = s1 * (1.f - wx);
                    acc.x = fmaf(cc, f0.x, acc.x); acc.y = fmaf(cc, f0.y, acc.y);
                    acc.z = fmaf(cc, f1.x, acc.z); acc.w = fmaf(cc, f1.y, acc.w);
                }
                if (vx1) {
                    uint2 u = vq[(size_t)(rowk + x0 + 1) * 64];
                    float2 f0 = __half22float2(*reinterpret_cast<__half2*>(&u.x));
                    float2 f1 = __half22float2(*reinterpret_cast<__half2*>(&u.y));
                    float cc = s1 * wx;
                    acc.x = fmaf(cc, f0.x, acc.x); acc.y = fmaf(cc, f0.y, acc.y);
                    acc.z = fmaf(cc, f1.x, acc.z); acc.w = fmaf(cc, f1.y, acc.w);
                }
            }
        }
    }
    // store channels 4li..4li+3 of head h
    out[(size_t)q * 64 + h * 8 + li] = acc;
}

// ---------------- host launch ----------------
static void* sym_addr(const void* sym)
{
    void* p = nullptr;
    cudaGetSymbolAddress(&p, sym);
    return p;
}

extern "C" void kernel_launch(void* const* d_in, const int* in_sizes, int n_in,
                              void* d_out, int out_size)
{
    const float* query     = (const float*)d_in[0];
    const float* query_pos = (const float*)d_in[1];
    const float* value     = (const float*)d_in[2];
    const float* refpts    = (const float*)d_in[3];
    // d_in[4]: spatial_shapes (int32) — compile-time constants here
    const float* W_value   = (const float*)d_in[5];
    const float* b_value   = (const float*)d_in[6];
    const float* W_off     = (const float*)d_in[7];
    const float* b_off     = (const float*)d_in[8];
    const float* W_attn    = (const float*)d_in[9];
    const float* b_attn    = (const float*)d_in[10];
    const float* W_out     = (const float*)d_in[11];
    const float* b_out     = (const float*)d_in[12];
    float* out = (float*)d_out;

    __half* vh  = (__half*)sym_addr(g_vh);
    float* oa   = (float*)sym_addr(g_oa);
    float* samp = (float*)sym_addr(g_samp);
    float* wcat = (float*)sym_addr(g_wcat);
    float* bcat = (float*)sym_addr(g_bcat);

    // 0) concat W_off/W_attn (+biases) for the merged GEMM
    prep_cat<<<384, 256>>>(W_off, b_off, W_attn, b_attn, wcat, bcat);

    // 1) v = value @ W_value^T + b_value  -> fp16 (sampling only consumer)
    {
        dim3 grid(256 / BN, NQ / BM);
        gemm_hmma<<<grid, 256>>>(value, nullptr, W_value, b_value, nullptr,
                                 nullptr, vh, 256);
    }
    // 2) [offsets | attn] = (query+query_pos) @ Wcat^T + bcat   (N=384)
    {
        dim3 grid(384 / BN, NQ / BM);
        gemm_hmma<<<grid, 256>>>(query, query_pos, wcat, bcat, nullptr,
                                 oa, nullptr, 384);
    }
    // 3) deformable sampling (softmax fused) -> samp
    {
        int warps = NQ * 2;                      // warp per (q, head-quad)
        int blocks = (warps * 32) / 256;         // 5440, exact
        sample_kernel<<<blocks, 256>>>((const uint2*)vh, refpts, oa,
                                       (float4*)samp);
    }
    // 4) out = samp @ W_out^T + b_out + query (residual), straight to d_out
    {
        dim3 grid(256 / BN, NQ / BM);
        gemm_hmma<<<grid, 256>>>(samp, nullptr, W_out, b_out, query,
                                 out, nullptr, 256);
    }
}

// round 8
// speedup vs baseline: 3.6914x; 1.1355x over previous
#include <cuda_runtime.h>
#include <cuda_fp16.h>
#include <math.h>
#include <stdint.h>

// ---------------- problem constants ----------------
#define NQ      21760          // num queries == num keys
#define EMBED   256
#define NH      8
#define NL      4
#define NP      4
#define KDIM    256            // K for all GEMMs

__device__ __constant__ int c_start[NL] = {0, 16384, 20480, 21504};
__device__ __constant__ int c_HW[NL]    = {128, 64, 32, 16};   // square levels

// ---------------- scratch (device globals; no allocations allowed) --------
// x-paired value buffer: per (key, head, li=ch/8): [x0: 8ch fp16 | x1: 8ch fp16]
// = 32 B. key stride = 8 heads * 4 li * 32 B = 1024 B. 22.3 MB total.
__device__ uint32_t g_pv  [NQ * 256];
__device__ __half   g_oah [NQ * 384];   // [offsets(256) | logits(128)] fp16
__device__ __half   g_samph[NQ * 256];  // sampled, fp16 (feeds out-GEMM)
__device__ float    g_wcat[384 * 256];  // concat W_off;W_attn
__device__ float    g_bcat[384];        // concat b_off;b_attn

// ---------------- prep: concatenate W_off/W_attn and biases ----------------
__global__ void __launch_bounds__(256) prep_cat(
    const float* __restrict__ Woff, const float* __restrict__ boff,
    const float* __restrict__ Wattn, const float* __restrict__ battn,
    float* __restrict__ Wcat, float* __restrict__ bcat)
{
    int i = blockIdx.x * blockDim.x + threadIdx.x;
    if (i < 256 * 256) Wcat[i] = Woff[i];
    else if (i < 384 * 256) Wcat[i] = Wattn[i - 256 * 256];
    if (i < 256) bcat[i] = boff[i];
    else if (i < 384) bcat[i] = battn[i - 256];
}

// ---------------- fp16 tensor-core GEMM (HMMA m16n8k16 + ldmatrix) --------
// C[M,N] = (A (+A2) | Ah) @ W[N,K]^T + bias (+ident). M%128==0, N%128==0.
// Output: float C, half Ch, or x-paired buffer Cpair (exactly one non-null).
#define BM 128
#define BN 128
#define BK 32
#define PITCH 40   // halves per smem row; 8-row LDSM phases hit distinct banks

__device__ __forceinline__ uint32_t pack2(float x, float y) {
    __half2 h = __floats2half2_rn(x, y);
    return *reinterpret_cast<uint32_t*>(&h);
}

__device__ __forceinline__ void ldsm_x4(uint32_t* r, const __half* p) {
    uint32_t a = (uint32_t)__cvta_generic_to_shared(p);
    asm volatile("ldmatrix.sync.aligned.m8n8.x4.shared.b16 {%0,%1,%2,%3}, [%4];"
                 : "=r"(r[0]), "=r"(r[1]), "=r"(r[2]), "=r"(r[3]) : "r"(a));
}

__device__ __forceinline__ void mma_f16(float* c, const uint32_t* a,
                                        uint32_t b0, uint32_t b1) {
    asm volatile(
        "mma.sync.aligned.m16n8k16.row.col.f32.f16.f16.f32 "
        "{%0,%1,%2,%3}, {%4,%5,%6,%7}, {%8,%9}, {%0,%1,%2,%3};"
        : "+f"(c[0]), "+f"(c[1]), "+f"(c[2]), "+f"(c[3])
        : "r"(a[0]), "r"(a[1]), "r"(a[2]), "r"(a[3]), "r"(b0), "r"(b1));
}

__global__ void __launch_bounds__(256, 2) gemm_hmma(
    const float* __restrict__ A, const float* __restrict__ A2,
    const __half* __restrict__ Ah,
    const float* __restrict__ W, const float* __restrict__ bias,
    const float* __restrict__ ident,
    float* __restrict__ C, __half* __restrict__ Ch,
    uint32_t* __restrict__ Cpair, int N)
{
    __shared__ __half As[2][BM][PITCH];
    __shared__ __half Ws[2][BN][PITCH];

    const int tid  = threadIdx.x;
    const int bx   = blockIdx.x;       // N tile
    const int by   = blockIdx.y;       // M tile
    const int warp = tid >> 5;
    const int lane = tid & 31;
    const int g    = lane >> 2;
    const int tig  = lane & 3;
    const int wm   = (warp >> 1) * 32;
    const int wn   = (warp & 1) * 64;

    // coalesced loader: pass p covers 32 rows; 8 lanes span one row's
    // BK-wide chunk. passes 0-3 -> A rows, 4-7 -> W rows.
    const int lrow8 = tid >> 3;        // 0..31
    const int kq    = tid & 7;
    const float*  arow  = A  ? A  + (size_t)(by * BM + lrow8) * KDIM + kq * 4 : nullptr;
    const float*  a2row = A2 ? A2 + (size_t)(by * BM + lrow8) * KDIM + kq * 4 : nullptr;
    const __half* ahrow = Ah ? Ah + (size_t)(by * BM + lrow8) * KDIM + kq * 4 : nullptr;
    const float*  wrow  = W + (size_t)(bx * BN + lrow8) * KDIM + kq * 4;

    uint2 pfh[8];

    auto load_chunk = [&](int k0) {
        #pragma unroll
        for (int pass = 0; pass < 4; pass++) {
            if (ahrow) {
                pfh[pass] = *reinterpret_cast<const uint2*>(
                    ahrow + (size_t)pass * 32 * KDIM + k0);
            } else {
                float4 x = *reinterpret_cast<const float4*>(
                    arow + (size_t)pass * 32 * KDIM + k0);
                if (a2row) {
                    float4 y = *reinterpret_cast<const float4*>(
                        a2row + (size_t)pass * 32 * KDIM + k0);
                    x.x += y.x; x.y += y.y; x.z += y.z; x.w += y.w;
                }
                pfh[pass] = make_uint2(pack2(x.x, x.y), pack2(x.z, x.w));
            }
        }
        #pragma unroll
        for (int pass = 0; pass < 4; pass++) {
            float4 x = *reinterpret_cast<const float4*>(
                wrow + (size_t)pass * 32 * KDIM + k0);
            pfh[4 + pass] = make_uint2(pack2(x.x, x.y), pack2(x.z, x.w));
        }
    };
    auto store_chunk = [&](int buf) {
        #pragma unroll
        for (int pass = 0; pass < 4; pass++)
            *reinterpret_cast<uint2*>(&As[buf][pass * 32 + lrow8][kq * 4]) = pfh[pass];
        #pragma unroll
        for (int pass = 0; pass < 4; pass++)
            *reinterpret_cast<uint2*>(&Ws[buf][pass * 32 + lrow8][kq * 4]) = pfh[4 + pass];
    };

    float acc[2][8][4];
    #pragma unroll
    for (int i = 0; i < 2; i++)
        #pragma unroll
        for (int j = 0; j < 8; j++)
            #pragma unroll
            for (int t = 0; t < 4; t++) acc[i][j][t] = 0.f;

    load_chunk(0);

    const int lrow16 = lane & 15;
    const int lk8    = (lane >> 4) << 3;

    #pragma unroll
    for (int c = 0; c < KDIM / BK; c++) {     // 8 chunks
        const int buf = c & 1;
        store_chunk(buf);
        __syncthreads();
        if (c < KDIM / BK - 1) load_chunk((c + 1) * BK);

        #pragma unroll
        for (int kk = 0; kk < BK; kk += 16) {
            uint32_t af[2][4];
            #pragma unroll
            for (int mf = 0; mf < 2; mf++)
                ldsm_x4(af[mf], &As[buf][wm + mf * 16 + lrow16][kk + lk8]);
            uint32_t bf[8][2];
            #pragma unroll
            for (int npg = 0; npg < 4; npg++) {
                uint32_t r[4];
                ldsm_x4(r, &Ws[buf][wn + npg * 16 + lrow16][kk + lk8]);
                bf[npg * 2 + 0][0] = r[0]; bf[npg * 2 + 0][1] = r[2];
                bf[npg * 2 + 1][0] = r[1]; bf[npg * 2 + 1][1] = r[3];
            }
            #pragma unroll
            for (int mf = 0; mf < 2; mf++)
                #pragma unroll
                for (int nf = 0; nf < 8; nf++)
                    mma_f16(acc[mf][nf], af[mf], bf[nf][0], bf[nf][1]);
        }
    }

    // ---------------- epilogue ----------------
    const int nb = bx * BN + wn;
    #pragma unroll
    for (int mf = 0; mf < 2; mf++) {
        #pragma unroll
        for (int hh = 0; hh < 2; hh++) {
            int m = by * BM + wm + mf * 16 + g + hh * 8;
            #pragma unroll
            for (int nf = 0; nf < 8; nf++) {
                int col = nb + nf * 8 + tig * 2;
                float2 bb = *reinterpret_cast<const float2*>(bias + col);
                float2 r;
                r.x = acc[mf][nf][hh * 2 + 0] + bb.x;
                r.y = acc[mf][nf][hh * 2 + 1] + bb.y;
                if (ident) {
                    float2 iv = *reinterpret_cast<const float2*>(
                        ident + (size_t)m * N + col);
                    r.x += iv.x; r.y += iv.y;
                }
                if (Cpair) {
                    // x-paired buffer: write to key m's x0 slot and key (m-1)'s x1 slot
                    uint32_t hw = pack2(r.x, r.y);
                    int ch = col & 31, hd = col >> 5;
                    int li = ch >> 3, w = (ch & 7) >> 1;
                    int base = (m * 32 + hd * 4 + li) * 8;
                    Cpair[base + w] = hw;
                    if (m > 0) Cpair[base - 256 + 4 + w] = hw;
                } else if (Ch) {
                    *reinterpret_cast<__half2*>(Ch + (size_t)m * N + col) =
                        __floats2half2_rn(r.x, r.y);
                } else {
                    *reinterpret_cast<float2*>(C + (size_t)m * N + col) = r;
                }
            }
        }
    }
}

// ---------------- deformable sampling + fused softmax ----------------
// Warp per query: 8 heads x 4 lanes; lane = 8 channels; lane li owns points
// 4li..4li+3 for softmax/offsets. Corner pairs (x0,x0+1) read as 32 B from g_pv.
__global__ void __launch_bounds__(256) sample_kernel(
    const uint4* __restrict__ pv, const float* __restrict__ ref,
    const __half* __restrict__ oah, uint4* __restrict__ samp4)
{
    const int q    = (blockIdx.x * blockDim.x + threadIdx.x) >> 5;
    const int lane = threadIdx.x & 31;
    if (q >= NQ) return;
    const int h  = lane >> 2;
    const int li = lane & 3;

    // offsets for points 4li..4li+3: 8 halves
    uint4 ov = *reinterpret_cast<const uint4*>(oah + (size_t)q * 384 + h * 32 + li * 8);
    float2 p0 = __half22float2(*reinterpret_cast<__half2*>(&ov.x));
    float2 p1 = __half22float2(*reinterpret_cast<__half2*>(&ov.y));
    float2 p2 = __half22float2(*reinterpret_cast<__half2*>(&ov.z));
    float2 p3 = __half22float2(*reinterpret_cast<__half2*>(&ov.w));
    float oxr[4] = {p0.x, p1.x, p2.x, p3.x};
    float oyr[4] = {p0.y, p1.y, p2.y, p3.y};

    // logits for points 4li..4li+3
    uint2 lv = *reinterpret_cast<const uint2*>(oah + (size_t)q * 384 + 256 + h * 16 + li * 4);
    float2 l0 = __half22float2(*reinterpret_cast<__half2*>(&lv.x));
    float2 l1 = __half22float2(*reinterpret_cast<__half2*>(&lv.y));
    float lg[4] = {l0.x, l0.y, l1.x, l1.y};

    // softmax over 16 points (4-lane groups)
    float mx = fmaxf(fmaxf(lg[0], lg[1]), fmaxf(lg[2], lg[3]));
    mx = fmaxf(mx, __shfl_xor_sync(0xffffffffu, mx, 1));
    mx = fmaxf(mx, __shfl_xor_sync(0xffffffffu, mx, 2));
    float wr[4];
    float s = 0.f;
    #pragma unroll
    for (int j = 0; j < 4; j++) { wr[j] = __expf(lg[j] - mx); s += wr[j]; }
    s += __shfl_xor_sync(0xffffffffu, s, 1);
    s += __shfl_xor_sync(0xffffffffu, s, 2);
    float inv = 1.f / s;
    #pragma unroll
    for (int j = 0; j < 4; j++) wr[j] *= inv;

    float acc[8] = {0.f, 0.f, 0.f, 0.f, 0.f, 0.f, 0.f, 0.f};

    auto accum = [&](uint4 u, float cc) {
        float2 f;
        f = __half22float2(*reinterpret_cast<__half2*>(&u.x));
        acc[0] = fmaf(cc, f.x, acc[0]); acc[1] = fmaf(cc, f.y, acc[1]);
        f = __half22float2(*reinterpret_cast<__half2*>(&u.y));
        acc[2] = fmaf(cc, f.x, acc[2]); acc[3] = fmaf(cc, f.y, acc[3]);
        f = __half22float2(*reinterpret_cast<__half2*>(&u.z));
        acc[4] = fmaf(cc, f.x, acc[4]); acc[5] = fmaf(cc, f.y, acc[5]);
        f = __half22float2(*reinterpret_cast<__half2*>(&u.w));
        acc[6] = fmaf(cc, f.x, acc[6]); acc[7] = fmaf(cc, f.y, acc[7]);
    };

    #pragma unroll
    for (int lvl = 0; lvl < NL; lvl++) {
        const int HW = c_HW[lvl];
        const int start = c_start[lvl];
        const float fHW = (float)HW;
        const float rx = ref[(size_t)q * 8 + lvl * 2 + 0];
        const float ry = ref[(size_t)q * 8 + lvl * 2 + 1];
        #pragma unroll
        for (int p = 0; p < NP; p++) {
            const int pt = lvl * 4 + p;                 // compile-time
            const int owner = (lane & ~3) | (pt >> 2);
            const int j = pt & 3;                        // compile-time
            float ox = __shfl_sync(0xffffffffu, oxr[j], owner);
            float oy = __shfl_sync(0xffffffffu, oyr[j], owner);
            float aw = __shfl_sync(0xffffffffu, wr[j],  owner);

            float gx = fmaf(rx, fHW, ox - 0.5f);
            float gy = fmaf(ry, fHW, oy - 0.5f);
            float x0f = floorf(gx), y0f = floorf(gy);
            float wx = gx - x0f, wy = gy - y0f;
            int x0 = (int)x0f, y0 = (int)y0f;

            bool vx0 = (unsigned)x0       < (unsigned)HW;
            bool vx1 = (unsigned)(x0 + 1) < (unsigned)HW;
            // first-half / second-half coefficients of the x-pair
            float Acf = vx0 ? (1.f - wx) : (vx1 ? wx : 0.f);
            float Bcf = (vx0 && vx1) ? wx : 0.f;
            float s0 = ((unsigned)y0       < (unsigned)HW) ? aw * (1.f - wy) : 0.f;
            float s1 = ((unsigned)(y0 + 1) < (unsigned)HW) ? aw * wy : 0.f;

            int xc  = min(max(x0, 0), HW - 1);
            int yc0 = min(max(y0, 0), HW - 1);
            int yc1 = min(max(y0 + 1, 0), HW - 1);
            int k0 = start + yc0 * HW + xc;
            int k1 = start + yc1 * HW + xc;

            size_t i0 = ((size_t)k0 * 32 + lane) * 2;
            size_t i1 = ((size_t)k1 * 32 + lane) * 2;
            uint4 u0a = pv[i0], u0b = pv[i0 + 1];
            uint4 u1a = pv[i1], u1b = pv[i1 + 1];
            accum(u0a, s0 * Acf); accum(u0b, s0 * Bcf);
            accum(u1a, s1 * Acf); accum(u1b, s1 * Bcf);
        }
    }

    // store 8 channels as fp16 (16 B)
    uint4 outv;
    outv.x = pack2(acc[0], acc[1]);
    outv.y = pack2(acc[2], acc[3]);
    outv.z = pack2(acc[4], acc[5]);
    outv.w = pack2(acc[6], acc[7]);
    samp4[(size_t)q * 32 + lane] = outv;
}

// ---------------- host launch ----------------
static void* sym_addr(const void* sym)
{
    void* p = nullptr;
    cudaGetSymbolAddress(&p, sym);
    return p;
}

extern "C" void kernel_launch(void* const* d_in, const int* in_sizes, int n_in,
                              void* d_out, int out_size)
{
    const float* query     = (const float*)d_in[0];
    const float* query_pos = (const float*)d_in[1];
    const float* value     = (const float*)d_in[2];
    const float* refpts    = (const float*)d_in[3];
    // d_in[4]: spatial_shapes (int32) — compile-time constants here
    const float* W_value   = (const float*)d_in[5];
    const float* b_value   = (const float*)d_in[6];
    const float* W_off     = (const float*)d_in[7];
    const float* b_off     = (const float*)d_in[8];
    const float* W_attn    = (const float*)d_in[9];
    const float* b_attn    = (const float*)d_in[10];
    const float* W_out     = (const float*)d_in[11];
    const float* b_out     = (const float*)d_in[12];
    float* out = (float*)d_out;

    uint32_t* pv    = (uint32_t*)sym_addr(g_pv);
    __half*   oah   = (__half*)sym_addr(g_oah);
    __half*   samph = (__half*)sym_addr(g_samph);
    float*    wcat  = (float*)sym_addr(g_wcat);
    float*    bcat  = (float*)sym_addr(g_bcat);

    // 0) concat W_off/W_attn (+biases) for the merged GEMM
    prep_cat<<<384, 256>>>(W_off, b_off, W_attn, b_attn, wcat, bcat);

    // 1) v = value @ W_value^T + b_value  -> x-paired fp16 buffer
    {
        dim3 grid(256 / BN, NQ / BM);
        gemm_hmma<<<grid, 256>>>(value, nullptr, nullptr, W_value, b_value,
                                 nullptr, nullptr, nullptr, pv, 256);
    }
    // 2) [offsets | logits] = (query+query_pos) @ Wcat^T + bcat -> fp16 (N=384)
    {
        dim3 grid(384 / BN, NQ / BM);
        gemm_hmma<<<grid, 256>>>(query, query_pos, nullptr, wcat, bcat,
                                 nullptr, nullptr, oah, nullptr, 384);
    }
    // 3) deformable sampling (softmax fused) -> samp fp16
    {
        int blocks = (NQ * 32) / 256;            // 2720, exact
        sample_kernel<<<blocks, 256>>>((const uint4*)pv, refpts, oah,
                                       (uint4*)samph);
    }
    // 4) out = samp @ W_out^T + b_out + query (residual), straight to d_out
    {
        dim3 grid(256 / BN, NQ / BM);
        gemm_hmma<<<grid, 256>>>(nullptr, nullptr, samph, W_out, b_out, query,
                                 out, nullptr, nullptr, 256);
    }
}

// round 9
// speedup vs baseline: 4.4313x; 1.2005x over previous
#include <cuda_runtime.h>
#include <cuda_fp16.h>
#include <math.h>
#include <stdint.h>

// ---------------- problem constants ----------------
#define NQ      21760          // num queries == num keys
#define EMBED   256
#define NH      8
#define NL      4
#define NP      4
#define KDIM    256            // K for all GEMMs

__device__ __constant__ int c_start[NL] = {0, 16384, 20480, 21504};
__device__ __constant__ int c_HW[NL]    = {128, 64, 32, 16};   // square levels

// ---------------- scratch (device globals; no allocations allowed) --------
// x-paired value buffer: per (key, head, li=ch/8): [x0: 8ch | x1: 8ch] fp16.
__device__ uint32_t g_pv   [NQ * 256];
__device__ __half   g_oah  [NQ * 384];   // [offsets(256) | logits(128)] fp16
__device__ __half   g_samph[NQ * 256];   // sampled fp16 (feeds out-GEMM)
__device__ __half   g_v16  [NQ * 256];   // value fp16
__device__ __half   g_q16  [NQ * 256];   // (query+query_pos) fp16
__device__ __half   g_wv16 [256 * 256];  // W_value fp16
__device__ __half   g_wcat16[384 * 256]; // concat W_off;W_attn fp16
__device__ __half   g_wout16[256 * 256]; // W_out fp16
__device__ float    g_bcat [384];        // concat b_off;b_attn fp32

// ---------------- prep: fp16 conversions + weight concat ----------------
__device__ __forceinline__ uint32_t pack2(float x, float y) {
    __half2 h = __floats2half2_rn(x, y);
    return *reinterpret_cast<uint32_t*>(&h);
}
__device__ __forceinline__ uint4 cvt8(const float* s) {
    float4 a = *reinterpret_cast<const float4*>(s);
    float4 b = *reinterpret_cast<const float4*>(s + 4);
    return make_uint4(pack2(a.x,a.y), pack2(a.z,a.w), pack2(b.x,b.y), pack2(b.z,b.w));
}
__device__ __forceinline__ uint4 cvt8sum(const float* s, const float* t) {
    float4 a = *reinterpret_cast<const float4*>(s);
    float4 b = *reinterpret_cast<const float4*>(s + 4);
    float4 c = *reinterpret_cast<const float4*>(t);
    float4 d = *reinterpret_cast<const float4*>(t + 4);
    a.x+=c.x; a.y+=c.y; a.z+=c.z; a.w+=c.w;
    b.x+=d.x; b.y+=d.y; b.z+=d.z; b.w+=d.w;
    return make_uint4(pack2(a.x,a.y), pack2(a.z,a.w), pack2(b.x,b.y), pack2(b.z,b.w));
}

#define NV8 (NQ * 256 / 8)   // 696320

__global__ void __launch_bounds__(256) prep_kernel(
    const float* __restrict__ query, const float* __restrict__ query_pos,
    const float* __restrict__ value,
    const float* __restrict__ Wv, const float* __restrict__ Woff,
    const float* __restrict__ Wattn, const float* __restrict__ Wout,
    const float* __restrict__ boff, const float* __restrict__ battn)
{
    int idx = blockIdx.x * 256 + threadIdx.x;
    const int r0 = NV8;                 // value
    const int r1 = 2 * NV8;             // q
    const int r2 = r1 + 8192;           // Wv (65536/8)
    const int r3 = r2 + 12288;          // Wcat (98304/8)
    const int r4 = r3 + 8192;           // Wout
    const int r5 = r4 + 48;             // bcat (384/8)

    if (idx < r0) {
        reinterpret_cast<uint4*>(g_v16)[idx] = cvt8(value + (size_t)idx * 8);
    } else if (idx < r1) {
        int i = idx - r0;
        reinterpret_cast<uint4*>(g_q16)[i] =
            cvt8sum(query + (size_t)i * 8, query_pos + (size_t)i * 8);
    } else if (idx < r2) {
        int i = idx - r1;
        reinterpret_cast<uint4*>(g_wv16)[i] = cvt8(Wv + (size_t)i * 8);
    } else if (idx < r3) {
        int i = idx - r2;
        int e = i * 8;
        reinterpret_cast<uint4*>(g_wcat16)[i] =
            (e < 65536) ? cvt8(Woff + e) : cvt8(Wattn + (e - 65536));
    } else if (idx < r4) {
        int i = idx - r3;
        reinterpret_cast<uint4*>(g_wout16)[i] = cvt8(Wout + (size_t)i * 8);
    } else if (idx < r5) {
        int i = idx - r4;
        int e = i * 8;
        #pragma unroll
        for (int j = 0; j < 8; j++) {
            int n = e + j;
            g_bcat[n] = (n < 256) ? boff[n] : battn[n - 256];
        }
    }
}

// ---------------- fp16 HMMA GEMM with cp.async pipeline ----------------
// C[M,N] = Ah[M,256] @ Wh[N,256]^T + bias (+ident). 128x128 tile, BK=64,
// 3-stage cp.async, XOR-swizzled smem (pitch 64 halves, chunk ^= row&7).
#define GBM 128
#define GBN 128
#define GBK 64
#define GS  3
#define NCH (KDIM / GBK)   // 4

__device__ __forceinline__ void cp16(uint32_t dst, const void* src) {
    asm volatile("cp.async.cg.shared.global [%0], [%1], 16;" :: "r"(dst), "l"(src));
}
__device__ __forceinline__ void cp_commit() {
    asm volatile("cp.async.commit_group;");
}
template <int n>
__device__ __forceinline__ void cp_wait() {
    asm volatile("cp.async.wait_group %0;" :: "n"(n));
}
__device__ __forceinline__ void ldsm_x4a(uint32_t* r, uint32_t addr) {
    asm volatile("ldmatrix.sync.aligned.m8n8.x4.shared.b16 {%0,%1,%2,%3}, [%4];"
                 : "=r"(r[0]), "=r"(r[1]), "=r"(r[2]), "=r"(r[3]) : "r"(addr));
}
__device__ __forceinline__ void mma_f16(float* c, const uint32_t* a,
                                        uint32_t b0, uint32_t b1) {
    asm volatile(
        "mma.sync.aligned.m16n8k16.row.col.f32.f16.f16.f32 "
        "{%0,%1,%2,%3}, {%4,%5,%6,%7}, {%8,%9}, {%0,%1,%2,%3};"
        : "+f"(c[0]), "+f"(c[1]), "+f"(c[2]), "+f"(c[3])
        : "r"(a[0]), "r"(a[1]), "r"(a[2]), "r"(a[3]), "r"(b0), "r"(b1));
}

extern __shared__ __half smx[];   // [GS][A:128x64 | W:128x64]

__global__ void __launch_bounds__(256, 2) gemm_dual(
    const __half* __restrict__ A0, const __half* __restrict__ W0,
    const float* __restrict__ b0, int N0,
    uint32_t* __restrict__ pair0, __half* __restrict__ h0,
    float* __restrict__ f0, const float* __restrict__ id0,
    const __half* __restrict__ A1, const __half* __restrict__ W1,
    const float* __restrict__ b1, int N1,
    uint32_t* __restrict__ pair1, __half* __restrict__ h1,
    float* __restrict__ f1, const float* __restrict__ id1,
    int split)
{
    int bx = blockIdx.x;
    const int by = blockIdx.y;
    const __half *Ag, *Wg; const float* bias; int N;
    uint32_t* Cpair; __half* Ch; float* Cf; const float* ident;
    if (bx < split) {
        Ag = A0; Wg = W0; bias = b0; N = N0;
        Cpair = pair0; Ch = h0; Cf = f0; ident = id0;
    } else {
        bx -= split;
        Ag = A1; Wg = W1; bias = b1; N = N1;
        Cpair = pair1; Ch = h1; Cf = f1; ident = id1;
    }

    const int tid  = threadIdx.x;
    const int warp = tid >> 5;
    const int lane = tid & 31;
    const int g    = lane >> 2;
    const int tig  = lane & 3;
    const int wm   = (warp >> 1) * 32;
    const int wn   = (warp & 1) * 64;
    const int lrow16 = lane & 15;
    const int lk8    = (lane >> 4) << 3;

    const uint32_t sbase = (uint32_t)__cvta_generic_to_shared(smx);

    const int lr = tid >> 3;     // 0..31 row within 32-row round
    const int cc = tid & 7;      // 16B chunk within 128B row slice
    const __half* Abase = Ag + (size_t)(by * GBM) * KDIM;
    const __half* Wbase = Wg + (size_t)(bx * GBN) * KDIM;

    auto load_stage = [&](int st, int kc) {
        const uint32_t sa = sbase + st * 32768;
        const int k0 = kc * GBK;
        #pragma unroll
        for (int r4 = 0; r4 < 4; r4++) {
            int row = r4 * 32 + lr;
            cp16(sa + (row * 64 + ((cc ^ (row & 7)) << 3)) * 2,
                 Abase + (size_t)row * KDIM + k0 + cc * 8);
        }
        #pragma unroll
        for (int r4 = 0; r4 < 4; r4++) {
            int row = r4 * 32 + lr;
            cp16(sa + 16384 + (row * 64 + ((cc ^ (row & 7)) << 3)) * 2,
                 Wbase + (size_t)row * KDIM + k0 + cc * 8);
        }
        cp_commit();
    };

    float acc[2][8][4];
    #pragma unroll
    for (int i = 0; i < 2; i++)
        #pragma unroll
        for (int j = 0; j < 8; j++)
            #pragma unroll
            for (int t = 0; t < 4; t++) acc[i][j][t] = 0.f;

    load_stage(0, 0);
    load_stage(1, 1);

    #pragma unroll
    for (int i = 0; i < NCH; i++) {
        if (i < NCH - 1) cp_wait<1>(); else cp_wait<0>();
        __syncthreads();
        const int st = i % GS;
        const uint32_t sa = sbase + st * 32768;

        #pragma unroll
        for (int kk = 0; kk < GBK; kk += 16) {
            const int hc = (kk + lk8) >> 3;          // 16B chunk index
            uint32_t af[2][4];
            #pragma unroll
            for (int mf = 0; mf < 2; mf++) {
                int row = wm + mf * 16 + lrow16;
                ldsm_x4a(af[mf], sa + (row * 64 + ((hc ^ (row & 7)) << 3)) * 2);
            }
            uint32_t bf[8][2];
            #pragma unroll
            for (int g4 = 0; g4 < 4; g4++) {
                int row = wn + g4 * 16 + lrow16;
                uint32_t r[4];
                ldsm_x4a(r, sa + 16384 + (row * 64 + ((hc ^ (row & 7)) << 3)) * 2);
                bf[g4 * 2 + 0][0] = r[0]; bf[g4 * 2 + 0][1] = r[2];
                bf[g4 * 2 + 1][0] = r[1]; bf[g4 * 2 + 1][1] = r[3];
            }
            #pragma unroll
            for (int mf = 0; mf < 2; mf++)
                #pragma unroll
                for (int nf = 0; nf < 8; nf++)
                    mma_f16(acc[mf][nf], af[mf], bf[nf][0], bf[nf][1]);
        }
        if (i + GS - 1 < NCH) load_stage((i + GS - 1) % GS, i + GS - 1);
    }

    // ---------------- epilogue ----------------
    const int nb = bx * GBN + wn;
    #pragma unroll
    for (int mf = 0; mf < 2; mf++) {
        #pragma unroll
        for (int hh = 0; hh < 2; hh++) {
            int m = by * GBM + wm + mf * 16 + g + hh * 8;
            #pragma unroll
            for (int nf = 0; nf < 8; nf++) {
                int col = nb + nf * 8 + tig * 2;
                float2 bb = *reinterpret_cast<const float2*>(bias + col);
                float2 r;
                r.x = acc[mf][nf][hh * 2 + 0] + bb.x;
                r.y = acc[mf][nf][hh * 2 + 1] + bb.y;
                if (ident) {
                    float2 iv = *reinterpret_cast<const float2*>(
                        ident + (size_t)m * N + col);
                    r.x += iv.x; r.y += iv.y;
                }
                if (Cpair) {
                    // x-paired buffer: key m's x0 slot and key (m-1)'s x1 slot
                    uint32_t hw = pack2(r.x, r.y);
                    int ch = col & 31, hd = col >> 5;
                    int li = ch >> 3, w = (ch & 7) >> 1;
                    int base = (m * 32 + hd * 4 + li) * 8;
                    Cpair[base + w] = hw;
                    if (m > 0) Cpair[base - 256 + 4 + w] = hw;
                } else if (Ch) {
                    *reinterpret_cast<__half2*>(Ch + (size_t)m * N + col) =
                        __floats2half2_rn(r.x, r.y);
                } else {
                    *reinterpret_cast<float2*>(Cf + (size_t)m * N + col) = r;
                }
            }
        }
    }
}

// ---------------- deformable sampling + fused softmax ----------------
// Warp per query: 8 heads x 4 lanes; lane = 8 channels; lane li owns points
// 4li..4li+3 for softmax/offsets. Corner pairs (x0,x0+1) read as 32 B from g_pv.
__global__ void __launch_bounds__(256) sample_kernel(
    const uint4* __restrict__ pv, const float* __restrict__ ref,
    const __half* __restrict__ oah, uint4* __restrict__ samp4)
{
    const int q    = (blockIdx.x * blockDim.x + threadIdx.x) >> 5;
    const int lane = threadIdx.x & 31;
    if (q >= NQ) return;
    const int h  = lane >> 2;
    const int li = lane & 3;

    uint4 ov = *reinterpret_cast<const uint4*>(oah + (size_t)q * 384 + h * 32 + li * 8);
    float2 p0 = __half22float2(*reinterpret_cast<__half2*>(&ov.x));
    float2 p1 = __half22float2(*reinterpret_cast<__half2*>(&ov.y));
    float2 p2 = __half22float2(*reinterpret_cast<__half2*>(&ov.z));
    float2 p3 = __half22float2(*reinterpret_cast<__half2*>(&ov.w));
    float oxr[4] = {p0.x, p1.x, p2.x, p3.x};
    float oyr[4] = {p0.y, p1.y, p2.y, p3.y};

    uint2 lv = *reinterpret_cast<const uint2*>(oah + (size_t)q * 384 + 256 + h * 16 + li * 4);
    float2 l0 = __half22float2(*reinterpret_cast<__half2*>(&lv.x));
    float2 l1 = __half22float2(*reinterpret_cast<__half2*>(&lv.y));
    float lg[4] = {l0.x, l0.y, l1.x, l1.y};

    float mx = fmaxf(fmaxf(lg[0], lg[1]), fmaxf(lg[2], lg[3]));
    mx = fmaxf(mx, __shfl_xor_sync(0xffffffffu, mx, 1));
    mx = fmaxf(mx, __shfl_xor_sync(0xffffffffu, mx, 2));
    float wr[4];
    float s = 0.f;
    #pragma unroll
    for (int j = 0; j < 4; j++) { wr[j] = __expf(lg[j] - mx); s += wr[j]; }
    s += __shfl_xor_sync(0xffffffffu, s, 1);
    s += __shfl_xor_sync(0xffffffffu, s, 2);
    float inv = 1.f / s;
    #pragma unroll
    for (int j = 0; j < 4; j++) wr[j] *= inv;

    float acc[8] = {0.f, 0.f, 0.f, 0.f, 0.f, 0.f, 0.f, 0.f};

    auto accum = [&](uint4 u, float cc) {
        float2 f;
        f = __half22float2(*reinterpret_cast<__half2*>(&u.x));
        acc[0] = fmaf(cc, f.x, acc[0]); acc[1] = fmaf(cc, f.y, acc[1]);
        f = __half22float2(*reinterpret_cast<__half2*>(&u.y));
        acc[2] = fmaf(cc, f.x, acc[2]); acc[3] = fmaf(cc, f.y, acc[3]);
        f = __half22float2(*reinterpret_cast<__half2*>(&u.z));
        acc[4] = fmaf(cc, f.x, acc[4]); acc[5] = fmaf(cc, f.y, acc[5]);
        f = __half22float2(*reinterpret_cast<__half2*>(&u.w));
        acc[6] = fmaf(cc, f.x, acc[6]); acc[7] = fmaf(cc, f.y, acc[7]);
    };

    #pragma unroll
    for (int lvl = 0; lvl < NL; lvl++) {
        const int HW = c_HW[lvl];
        const int start = c_start[lvl];
        const float fHW = (float)HW;
        const float rx = ref[(size_t)q * 8 + lvl * 2 + 0];
        const float ry = ref[(size_t)q * 8 + lvl * 2 + 1];
        #pragma unroll
        for (int p = 0; p < NP; p++) {
            const int pt = lvl * 4 + p;
            const int owner = (lane & ~3) | (pt >> 2);
            const int j = pt & 3;
            float ox = __shfl_sync(0xffffffffu, oxr[j], owner);
            float oy = __shfl_sync(0xffffffffu, oyr[j], owner);
            float aw = __shfl_sync(0xffffffffu, wr[j],  owner);

            float gx = fmaf(rx, fHW, ox - 0.5f);
            float gy = fmaf(ry, fHW, oy - 0.5f);
            float x0f = floorf(gx), y0f = floorf(gy);
            float wx = gx - x0f, wy = gy - y0f;
            int x0 = (int)x0f, y0 = (int)y0f;

            bool vx0 = (unsigned)x0       < (unsigned)HW;
            bool vx1 = (unsigned)(x0 + 1) < (unsigned)HW;
            float Acf = vx0 ? (1.f - wx) : (vx1 ? wx : 0.f);
            float Bcf = (vx0 && vx1) ? wx : 0.f;
            float s0 = ((unsigned)y0       < (unsigned)HW) ? aw * (1.f - wy) : 0.f;
            float s1 = ((unsigned)(y0 + 1) < (unsigned)HW) ? aw * wy : 0.f;

            int xc  = min(max(x0, 0), HW - 1);
            int yc0 = min(max(y0, 0), HW - 1);
            int yc1 = min(max(y0 + 1, 0), HW - 1);
            int k0 = start + yc0 * HW + xc;
            int k1 = start + yc1 * HW + xc;

            size_t i0 = ((size_t)k0 * 32 + lane) * 2;
            size_t i1 = ((size_t)k1 * 32 + lane) * 2;
            uint4 u0a = pv[i0], u0b = pv[i0 + 1];
            uint4 u1a = pv[i1], u1b = pv[i1 + 1];
            accum(u0a, s0 * Acf); accum(u0b, s0 * Bcf);
            accum(u1a, s1 * Acf); accum(u1b, s1 * Bcf);
        }
    }

    uint4 outv;
    outv.x = pack2(acc[0], acc[1]);
    outv.y = pack2(acc[2], acc[3]);
    outv.z = pack2(acc[4], acc[5]);
    outv.w = pack2(acc[6], acc[7]);
    samp4[(size_t)q * 32 + lane] = outv;
}

// ---------------- host launch ----------------
static void* sym_addr(const void* sym)
{
    void* p = nullptr;
    cudaGetSymbolAddress(&p, sym);
    return p;
}

extern "C" void kernel_launch(void* const* d_in, const int* in_sizes, int n_in,
                              void* d_out, int out_size)
{
    const float* query     = (const float*)d_in[0];
    const float* query_pos = (const float*)d_in[1];
    const float* value     = (const float*)d_in[2];
    const float* refpts    = (const float*)d_in[3];
    // d_in[4]: spatial_shapes (int32) — compile-time constants here
    const float* W_value   = (const float*)d_in[5];
    const float* b_value   = (const float*)d_in[6];
    const float* W_off     = (const float*)d_in[7];
    const float* b_off     = (const float*)d_in[8];
    const float* W_attn    = (const float*)d_in[9];
    const float* b_attn    = (const float*)d_in[10];
    const float* W_out     = (const float*)d_in[11];
    const float* b_out     = (const float*)d_in[12];
    float* out = (float*)d_out;

    uint32_t* pv     = (uint32_t*)sym_addr(g_pv);
    __half*   oah    = (__half*)sym_addr(g_oah);
    __half*   samph  = (__half*)sym_addr(g_samph);
    __half*   v16    = (__half*)sym_addr(g_v16);
    __half*   q16    = (__half*)sym_addr(g_q16);
    __half*   wv16   = (__half*)sym_addr(g_wv16);
    __half*   wcat16 = (__half*)sym_addr(g_wcat16);
    __half*   wout16 = (__half*)sym_addr(g_wout16);
    float*    bcat   = (float*)sym_addr(g_bcat);

    cudaFuncSetAttribute(gemm_dual,
                         cudaFuncAttributeMaxDynamicSharedMemorySize, 98304);

    // 0) fp16 conversions + weight concat
    {
        int total = 2 * NV8 + 8192 + 12288 + 8192 + 48;
        prep_kernel<<<(total + 255) / 256, 256>>>(
            query, query_pos, value, W_value, W_off, W_attn, W_out,
            b_off, b_attn);
    }
    // 1+2) merged: v = value@Wv^T -> pair buffer (bx 0..1)
    //              [off|logits] = q@Wcat^T -> oah   (bx 2..4)
    {
        dim3 grid(2 + 3, NQ / GBM);
        gemm_dual<<<grid, 256, 98304>>>(
            v16, wv16, b_value, 256, pv, nullptr, nullptr, nullptr,
            q16, wcat16, bcat, 384, nullptr, oah, nullptr, nullptr,
            2);
    }
    // 3) deformable sampling (softmax fused) -> samp fp16
    {
        int blocks = (NQ * 32) / 256;            // 2720, exact
        sample_kernel<<<blocks, 256>>>((const uint4*)pv, refpts, oah,
                                       (uint4*)samph);
    }
    // 4) out = samp @ W_out^T + b_out + query (residual) -> d_out (float)
    {
        dim3 grid(2, NQ / GBM);
        gemm_dual<<<grid, 256, 98304>>>(
            samph, wout16, b_out, 256, nullptr, nullptr, out, query,
            samph, wout16, b_out, 256, nullptr, nullptr, out, query,
            2);
    }
}

// round 10
// speedup vs baseline: 4.5359x; 1.0236x over previous
#include <cuda_runtime.h>
#include <cuda_fp16.h>
#include <math.h>
#include <stdint.h>

// ---------------- problem constants ----------------
#define NQ      21760          // num queries == num keys
#define EMBED   256
#define NH      8
#define NL      4
#define NP      4
#define KDIM    256            // K for all GEMMs

__device__ __constant__ int c_start[NL] = {0, 16384, 20480, 21504};
__device__ __constant__ int c_HW[NL]    = {128, 64, 32, 16};   // square levels

// ---------------- scratch (device globals; no allocations allowed) --------
// x-paired value buffer: per (key, head): [x0: 32ch (64B) | x1: 32ch (64B)].
__device__ uint32_t g_pv   [NQ * 256];
__device__ __half   g_oah  [NQ * 384];   // [offsets(256) | logits(128)] fp16
__device__ __half   g_samph[NQ * 256];   // sampled fp16 (feeds out-GEMM)
__device__ __half   g_v16  [NQ * 256];   // value fp16
__device__ __half   g_q16  [NQ * 256];   // (query+query_pos) fp16
__device__ __half   g_wv16 [256 * 256];  // W_value fp16
__device__ __half   g_wcat16[384 * 256]; // concat W_off;W_attn fp16
__device__ __half   g_wout16[256 * 256]; // W_out fp16
__device__ float    g_bcat [384];        // concat b_off;b_attn fp32

// ---------------- prep: fp16 conversions + weight concat ----------------
__device__ __forceinline__ uint32_t pack2(float x, float y) {
    __half2 h = __floats2half2_rn(x, y);
    return *reinterpret_cast<uint32_t*>(&h);
}
__device__ __forceinline__ uint4 cvt8(const float* s) {
    float4 a = *reinterpret_cast<const float4*>(s);
    float4 b = *reinterpret_cast<const float4*>(s + 4);
    return make_uint4(pack2(a.x,a.y), pack2(a.z,a.w), pack2(b.x,b.y), pack2(b.z,b.w));
}
__device__ __forceinline__ uint4 cvt8sum(const float* s, const float* t) {
    float4 a = *reinterpret_cast<const float4*>(s);
    float4 b = *reinterpret_cast<const float4*>(s + 4);
    float4 c = *reinterpret_cast<const float4*>(t);
    float4 d = *reinterpret_cast<const float4*>(t + 4);
    a.x+=c.x; a.y+=c.y; a.z+=c.z; a.w+=c.w;
    b.x+=d.x; b.y+=d.y; b.z+=d.z; b.w+=d.w;
    return make_uint4(pack2(a.x,a.y), pack2(a.z,a.w), pack2(b.x,b.y), pack2(b.z,b.w));
}

#define NV8 (NQ * 256 / 8)   // 696320

__global__ void __launch_bounds__(256) prep_kernel(
    const float* __restrict__ query, const float* __restrict__ query_pos,
    const float* __restrict__ value,
    const float* __restrict__ Wv, const float* __restrict__ Woff,
    const float* __restrict__ Wattn, const float* __restrict__ Wout,
    const float* __restrict__ boff, const float* __restrict__ battn)
{
    int idx = blockIdx.x * 256 + threadIdx.x;
    const int r0 = NV8;                 // value
    const int r1 = 2 * NV8;             // q
    const int r2 = r1 + 8192;           // Wv
    const int r3 = r2 + 12288;          // Wcat
    const int r4 = r3 + 8192;           // Wout
    const int r5 = r4 + 48;             // bcat

    if (idx < r0) {
        reinterpret_cast<uint4*>(g_v16)[idx] = cvt8(value + (size_t)idx * 8);
    } else if (idx < r1) {
        int i = idx - r0;
        reinterpret_cast<uint4*>(g_q16)[i] =
            cvt8sum(query + (size_t)i * 8, query_pos + (size_t)i * 8);
    } else if (idx < r2) {
        int i = idx - r1;
        reinterpret_cast<uint4*>(g_wv16)[i] = cvt8(Wv + (size_t)i * 8);
    } else if (idx < r3) {
        int i = idx - r2;
        int e = i * 8;
        reinterpret_cast<uint4*>(g_wcat16)[i] =
            (e < 65536) ? cvt8(Woff + e) : cvt8(Wattn + (e - 65536));
    } else if (idx < r4) {
        int i = idx - r3;
        reinterpret_cast<uint4*>(g_wout16)[i] = cvt8(Wout + (size_t)i * 8);
    } else if (idx < r5) {
        int i = idx - r4;
        int e = i * 8;
        #pragma unroll
        for (int jj = 0; jj < 8; jj++) {
            int n = e + jj;
            g_bcat[n] = (n < 256) ? boff[n] : battn[n - 256];
        }
    }
}

// ---------------- fp16 HMMA GEMM, 128x64 tile, cp.async 3-stage ----------
#define GBM 128
#define GBN 64
#define GBK 64
#define GS  3
#define NCH (KDIM / GBK)      // 4
#define STAGE_B 24576         // A 16KB + W 8KB
#define W_OFF   16384

__device__ __forceinline__ void cp16(uint32_t dst, const void* src) {
    asm volatile("cp.async.cg.shared.global [%0], [%1], 16;" :: "r"(dst), "l"(src));
}
__device__ __forceinline__ void cp_commit() {
    asm volatile("cp.async.commit_group;");
}
template <int n>
__device__ __forceinline__ void cp_wait() {
    asm volatile("cp.async.wait_group %0;" :: "n"(n));
}
__device__ __forceinline__ void ldsm_x4a(uint32_t* r, uint32_t addr) {
    asm volatile("ldmatrix.sync.aligned.m8n8.x4.shared.b16 {%0,%1,%2,%3}, [%4];"
                 : "=r"(r[0]), "=r"(r[1]), "=r"(r[2]), "=r"(r[3]) : "r"(addr));
}
__device__ __forceinline__ void mma_f16(float* c, const uint32_t* a,
                                        uint32_t b0, uint32_t b1) {
    asm volatile(
        "mma.sync.aligned.m16n8k16.row.col.f32.f16.f16.f32 "
        "{%0,%1,%2,%3}, {%4,%5,%6,%7}, {%8,%9}, {%0,%1,%2,%3};"
        : "+f"(c[0]), "+f"(c[1]), "+f"(c[2]), "+f"(c[3])
        : "r"(a[0]), "r"(a[1]), "r"(a[2]), "r"(a[3]), "r"(b0), "r"(b1));
}

extern __shared__ __half smx[];

__device__ __forceinline__ uint32_t swadr(uint32_t base, int row, int hc) {
    return base + (uint32_t)(row * 64 + ((hc ^ (row & 7)) << 3)) * 2;
}

__global__ void __launch_bounds__(256, 3) gemm_dual(
    const __half* __restrict__ A0, const __half* __restrict__ W0,
    const float* __restrict__ b0, int N0,
    uint32_t* __restrict__ pair0, __half* __restrict__ h0,
    float* __restrict__ f0, const float* __restrict__ id0,
    const __half* __restrict__ A1, const __half* __restrict__ W1,
    const float* __restrict__ b1, int N1,
    uint32_t* __restrict__ pair1, __half* __restrict__ h1,
    float* __restrict__ f1, const float* __restrict__ id1,
    int split)
{
    int bx = blockIdx.x;
    const int by = blockIdx.y;
    const __half *Ag, *Wg; const float* bias; int N;
    uint32_t* Cpair; __half* Ch; float* Cf; const float* ident;
    if (bx < split) {
        Ag = A0; Wg = W0; bias = b0; N = N0;
        Cpair = pair0; Ch = h0; Cf = f0; ident = id0;
    } else {
        bx -= split;
        Ag = A1; Wg = W1; bias = b1; N = N1;
        Cpair = pair1; Ch = h1; Cf = f1; ident = id1;
    }

    const int tid  = threadIdx.x;
    const int warp = tid >> 5;
    const int lane = tid & 31;
    const int g    = lane >> 2;
    const int tig  = lane & 3;
    const int wm   = (warp >> 1) * 32;   // 4 M-groups of 32
    const int wn   = (warp & 1) * 32;    // 2 N-groups of 32
    const int lrow16 = lane & 15;
    const int lk8    = (lane >> 4) << 3;

    const uint32_t sbase = (uint32_t)__cvta_generic_to_shared(smx);

    const int lr = tid >> 3;     // 0..31
    const int cc = tid & 7;      // 16B chunk in 128B slice
    const __half* Abase = Ag + (size_t)(by * GBM) * KDIM;
    const __half* Wbase = Wg + (size_t)(bx * GBN) * KDIM;

    auto load_stage = [&](int st, int kc) {
        const uint32_t sa = sbase + st * STAGE_B;
        const int k0 = kc * GBK;
        #pragma unroll
        for (int r4 = 0; r4 < 4; r4++) {
            int row = r4 * 32 + lr;
            cp16(swadr(sa, row, cc), Abase + (size_t)row * KDIM + k0 + cc * 8);
        }
        #pragma unroll
        for (int r2 = 0; r2 < 2; r2++) {
            int row = r2 * 32 + lr;
            cp16(swadr(sa + W_OFF, row, cc), Wbase + (size_t)row * KDIM + k0 + cc * 8);
        }
        cp_commit();
    };

    float acc[2][4][4];
    #pragma unroll
    for (int i = 0; i < 2; i++)
        #pragma unroll
        for (int jx = 0; jx < 4; jx++)
            #pragma unroll
            for (int t = 0; t < 4; t++) acc[i][jx][t] = 0.f;

    load_stage(0, 0);
    load_stage(1, 1);

    #pragma unroll
    for (int i = 0; i < NCH; i++) {
        if (i < NCH - 1) cp_wait<1>(); else cp_wait<0>();
        __syncthreads();
        const int st = i % GS;
        const uint32_t sa = sbase + st * STAGE_B;

        #pragma unroll
        for (int kk = 0; kk < GBK; kk += 16) {
            const int hc = (kk + lk8) >> 3;
            uint32_t af[2][4];
            #pragma unroll
            for (int mf = 0; mf < 2; mf++)
                ldsm_x4a(af[mf], swadr(sa, wm + mf * 16 + lrow16, hc));
            uint32_t bf[4][2];
            #pragma unroll
            for (int g4 = 0; g4 < 2; g4++) {
                uint32_t r[4];
                ldsm_x4a(r, swadr(sa + W_OFF, wn + g4 * 16 + lrow16, hc));
                bf[g4 * 2 + 0][0] = r[0]; bf[g4 * 2 + 0][1] = r[2];
                bf[g4 * 2 + 1][0] = r[1]; bf[g4 * 2 + 1][1] = r[3];
            }
            #pragma unroll
            for (int mf = 0; mf < 2; mf++)
                #pragma unroll
                for (int nf = 0; nf < 4; nf++)
                    mma_f16(acc[mf][nf], af[mf], bf[nf][0], bf[nf][1]);
        }
        if (i + GS - 1 < NCH) load_stage((i + GS - 1) % GS, i + GS - 1);
    }

    // ---------------- epilogue ----------------
    const int nb = bx * GBN + wn;
    #pragma unroll
    for (int mf = 0; mf < 2; mf++) {
        #pragma unroll
        for (int hh = 0; hh < 2; hh++) {
            int m = by * GBM + wm + mf * 16 + g + hh * 8;
            #pragma unroll
            for (int nf = 0; nf < 4; nf++) {
                int col = nb + nf * 8 + tig * 2;
                float2 bb = *reinterpret_cast<const float2*>(bias + col);
                float2 r;
                r.x = acc[mf][nf][hh * 2 + 0] + bb.x;
                r.y = acc[mf][nf][hh * 2 + 1] + bb.y;
                if (ident) {
                    float2 iv = *reinterpret_cast<const float2*>(
                        ident + (size_t)m * N + col);
                    r.x += iv.x; r.y += iv.y;
                }
                if (Cpair) {
                    // layout per (key, head): [x0: 16 u32 | x1: 16 u32]
                    uint32_t hw = pack2(r.x, r.y);
                    int ch = col & 31, hd = col >> 5;
                    int w = ch >> 1;
                    int base = (m * 8 + hd) * 32 + w;
                    Cpair[base] = hw;                       // x0 slot of key m
                    if (m > 0) Cpair[base - 256 + 16] = hw; // x1 slot of key m-1
                } else if (Ch) {
                    *reinterpret_cast<__half2*>(Ch + (size_t)m * N + col) =
                        __floats2half2_rn(r.x, r.y);
                } else {
                    *reinterpret_cast<float2*>(Cf + (size_t)m * N + col) = r;
                }
            }
        }
    }
}

// ---------------- deformable sampling + fused softmax ----------------
// Warp per (q, head-quad): 8 lanes/head. Lane j: j<4 accumulates x0-slot
// contribution for channels 8j..8j+7; j>=4 the x1-slot for channels 8(j-4)...
// Lane j owns points 2j, 2j+1: computes coords once, broadcasts k0,k1 + 4 coefs.
__global__ void __launch_bounds__(256) sample_kernel(
    const uint4* __restrict__ pv4, const float* __restrict__ ref,
    const __half* __restrict__ oah, uint4* __restrict__ samp4)
{
    const int gwarp = (blockIdx.x * blockDim.x + threadIdx.x) >> 5;
    const int lane = threadIdx.x & 31;
    if (gwarp >= NQ * 2) return;
    const int q  = gwarp >> 1;
    const int hq = gwarp & 1;
    const int h4 = lane >> 3;
    const int j  = lane & 7;
    const int h  = hq * 4 + h4;
    const bool isA = (j < 4);

    // offsets for points 2j, 2j+1: (ox0,oy0,ox1,oy1) as 4 halves
    uint2 ov = *reinterpret_cast<const uint2*>(oah + (size_t)q * 384 + h * 32 + j * 4);
    float2 o0 = __half22float2(*reinterpret_cast<__half2*>(&ov.x));
    float2 o1 = __half22float2(*reinterpret_cast<__half2*>(&ov.y));
    // logits for points 2j, 2j+1
    uint32_t lvu = *reinterpret_cast<const uint32_t*>(
        oah + (size_t)q * 384 + 256 + h * 16 + j * 2);
    float2 lg = __half22float2(*reinterpret_cast<__half2*>(&lvu));

    // softmax over 16 points (8-lane group)
    float mx = fmaxf(lg.x, lg.y);
    mx = fmaxf(mx, __shfl_xor_sync(0xffffffffu, mx, 1));
    mx = fmaxf(mx, __shfl_xor_sync(0xffffffffu, mx, 2));
    mx = fmaxf(mx, __shfl_xor_sync(0xffffffffu, mx, 4));
    float e0 = __expf(lg.x - mx), e1 = __expf(lg.y - mx);
    float s = e0 + e1;
    s += __shfl_xor_sync(0xffffffffu, s, 1);
    s += __shfl_xor_sync(0xffffffffu, s, 2);
    s += __shfl_xor_sync(0xffffffffu, s, 4);
    float inv = 1.f / s;
    float w0 = e0 * inv, w1 = e1 * inv;

    // owner precompute for owned points 2j (t=0), 2j+1 (t=1)
    int   K0[2], K1[2];
    float CA0[2], CB0[2], CA1[2], CB1[2];
    #pragma unroll
    for (int t = 0; t < 2; t++) {
        int ptm = 2 * j + t;
        int lvl = ptm >> 2;
        int HW = c_HW[lvl];
        int start = c_start[lvl];
        float fHW = (float)HW;
        float rx = ref[(size_t)q * 8 + lvl * 2 + 0];
        float ry = ref[(size_t)q * 8 + lvl * 2 + 1];
        float ox = t ? o1.x : o0.x;
        float oy = t ? o1.y : o0.y;
        float aw = t ? w1 : w0;

        float gx = fmaf(rx, fHW, ox - 0.5f);
        float gy = fmaf(ry, fHW, oy - 0.5f);
        float x0f = floorf(gx), y0f = floorf(gy);
        float wx = gx - x0f, wy = gy - y0f;
        int x0 = (int)x0f, y0 = (int)y0f;

        bool vx0 = (unsigned)x0       < (unsigned)HW;
        bool vx1 = (unsigned)(x0 + 1) < (unsigned)HW;
        float Acf = vx0 ? (1.f - wx) : (vx1 ? wx : 0.f);
        float Bcf = (vx0 && vx1) ? wx : 0.f;
        float s0 = ((unsigned)y0       < (unsigned)HW) ? aw * (1.f - wy) : 0.f;
        float s1 = ((unsigned)(y0 + 1) < (unsigned)HW) ? aw * wy : 0.f;

        int xc  = min(max(x0, 0), HW - 1);
        int yc0 = min(max(y0, 0), HW - 1);
        int yc1 = min(max(y0 + 1, 0), HW - 1);
        K0[t] = start + yc0 * HW + xc;
        K1[t] = start + yc1 * HW + xc;
        CA0[t] = s0 * Acf; CB0[t] = s0 * Bcf;
        CA1[t] = s1 * Acf; CB1[t] = s1 * Bcf;
    }

    float acc[8] = {0.f, 0.f, 0.f, 0.f, 0.f, 0.f, 0.f, 0.f};

    auto accum = [&](uint4 u, float cc) {
        float2 f;
        f = __half22float2(*reinterpret_cast<__half2*>(&u.x));
        acc[0] = fmaf(cc, f.x, acc[0]); acc[1] = fmaf(cc, f.y, acc[1]);
        f = __half22float2(*reinterpret_cast<__half2*>(&u.y));
        acc[2] = fmaf(cc, f.x, acc[2]); acc[3] = fmaf(cc, f.y, acc[3]);
        f = __half22float2(*reinterpret_cast<__half2*>(&u.z));
        acc[4] = fmaf(cc, f.x, acc[4]); acc[5] = fmaf(cc, f.y, acc[5]);
        f = __half22float2(*reinterpret_cast<__half2*>(&u.w));
        acc[6] = fmaf(cc, f.x, acc[6]); acc[7] = fmaf(cc, f.y, acc[7]);
    };

    #pragma unroll
    for (int pt = 0; pt < 16; pt++) {
        const int owner = (lane & 24) | (pt >> 1);
        const int t = pt & 1;                         // compile-time
        int   k0  = __shfl_sync(0xffffffffu, K0[t],  owner);
        int   k1  = __shfl_sync(0xffffffffu, K1[t],  owner);
        float ca0 = __shfl_sync(0xffffffffu, CA0[t], owner);
        float cb0 = __shfl_sync(0xffffffffu, CB0[t], owner);
        float ca1 = __shfl_sync(0xffffffffu, CA1[t], owner);
        float cb1 = __shfl_sync(0xffffffffu, CB1[t], owner);
        float c0 = isA ? ca0 : cb0;
        float c1 = isA ? ca1 : cb1;
        uint4 u0 = pv4[(size_t)(k0 * 8 + h) * 8 + j];
        uint4 u1 = pv4[(size_t)(k1 * 8 + h) * 8 + j];
        accum(u0, c0);
        accum(u1, c1);
    }

    // combine x0 (lanes j<4) and x1 (lanes j>=4) partial sums
    #pragma unroll
    for (int i = 0; i < 8; i++)
        acc[i] += __shfl_xor_sync(0xffffffffu, acc[i], 4);

    if (isA) {
        uint4 outv;
        outv.x = pack2(acc[0], acc[1]);
        outv.y = pack2(acc[2], acc[3]);
        outv.z = pack2(acc[4], acc[5]);
        outv.w = pack2(acc[6], acc[7]);
        samp4[(size_t)q * 32 + h * 4 + j] = outv;   // channels 8j..8j+7 of head h
    }
}

// ---------------- host launch ----------------
static void* sym_addr(const void* sym)
{
    void* p = nullptr;
    cudaGetSymbolAddress(&p, sym);
    return p;
}

extern "C" void kernel_launch(void* const* d_in, const int* in_sizes, int n_in,
                              void* d_out, int out_size)
{
    const float* query     = (const float*)d_in[0];
    const float* query_pos = (const float*)d_in[1];
    const float* value     = (const float*)d_in[2];
    const float* refpts    = (const float*)d_in[3];
    // d_in[4]: spatial_shapes (int32) — compile-time constants here
    const float* W_value   = (const float*)d_in[5];
    const float* b_value   = (const float*)d_in[6];
    const float* W_off     = (const float*)d_in[7];
    const float* b_off     = (const float*)d_in[8];
    const float* W_attn    = (const float*)d_in[9];
    const float* b_attn    = (const float*)d_in[10];
    const float* W_out     = (const float*)d_in[11];
    const float* b_out     = (const float*)d_in[12];
    float* out = (float*)d_out;

    uint32_t* pv     = (uint32_t*)sym_addr(g_pv);
    __half*   oah    = (__half*)sym_addr(g_oah);
    __half*   samph  = (__half*)sym_addr(g_samph);
    __half*   v16    = (__half*)sym_addr(g_v16);
    __half*   q16    = (__half*)sym_addr(g_q16);
    __half*   wv16   = (__half*)sym_addr(g_wv16);
    __half*   wcat16 = (__half*)sym_addr(g_wcat16);
    __half*   wout16 = (__half*)sym_addr(g_wout16);
    float*    bcat   = (float*)sym_addr(g_bcat);

    cudaFuncSetAttribute(gemm_dual,
                         cudaFuncAttributeMaxDynamicSharedMemorySize, GS * STAGE_B);

    // 0) fp16 conversions + weight concat
    {
        int total = 2 * NV8 + 8192 + 12288 + 8192 + 48;
        prep_kernel<<<(total + 255) / 256, 256>>>(
            query, query_pos, value, W_value, W_off, W_attn, W_out,
            b_off, b_attn);
    }
    // 1+2) merged: v = value@Wv^T -> pair buffer (bx 0..3, N=256)
    //              [off|logits] = q@Wcat^T -> oah   (bx 4..9, N=384)
    {
        dim3 grid(4 + 6, NQ / GBM);
        gemm_dual<<<grid, 256, GS * STAGE_B>>>(
            v16, wv16, b_value, 256, pv, nullptr, nullptr, nullptr,
            q16, wcat16, bcat, 384, nullptr, oah, nullptr, nullptr,
            4);
    }
    // 3) deformable sampling (softmax fused) -> samp fp16
    {
        int blocks = (NQ * 2 * 32) / 256;        // 5440, exact
        sample_kernel<<<blocks, 256>>>((const uint4*)pv, refpts, oah,
                                       (uint4*)samph);
    }
    // 4) out = samp @ W_out^T + b_out + query (residual) -> d_out (float)
    {
        dim3 grid(4, NQ / GBM);
        gemm_dual<<<grid, 256, GS * STAGE_B>>>(
            samph, wout16, b_out, 256, nullptr, nullptr, out, query,
            samph, wout16, b_out, 256, nullptr, nullptr, out, query,
            4);
    }
}